// round 8
// baseline (speedup 1.0000x reference)
#include <cuda_runtime.h>
#include <math.h>

// Problem constants
#define BB   16
#define SS   257
#define DD   1024
#define HH   16
#define DHH  64
#define FFD  4096
#define LLN  6
#define PPP  14
#define NPS  16
#define NP   256
#define KC   (3*14*14)   // 588 im2col K
#define MM   (BB*SS)     // 4112 rows
#define LNEPS 1e-5f

// ---------------- scratch ----------------------------------------------------
__device__ float g_col [BB*NP*KC];
__device__ float g_feat[BB*NP*DD];
__device__ float g_h   [MM*DD];
__device__ float g_q   [MM*DD];
__device__ float g_k   [MM*DD];
__device__ float g_v   [MM*DD];
__device__ float g_ctx [MM*DD];
__device__ float g_att [(size_t)BB*HH*SS*SS];
__device__ float g_ff  [(size_t)MM*FFD];
// tf32-rounded weights
__device__ float g_wq [LLN*DD*DD];
__device__ float g_wk [LLN*DD*DD];
__device__ float g_wv [LLN*DD*DD];
__device__ float g_wo [LLN*DD*DD];
__device__ float g_wf1[(size_t)LLN*FFD*DD];
__device__ float g_wf2[(size_t)LLN*FFD*DD];

__device__ __forceinline__ unsigned f2tf(float x) {
    unsigned r;
    asm("cvt.rna.tf32.f32 %0, %1;" : "=r"(r) : "f"(x));
    return r;
}

// ---------------- round-to-tf32 copy (weights) -------------------------------
__global__ void k_round(const float* __restrict__ s, float* __restrict__ d, int n4) {
    int i = blockIdx.x * blockDim.x + threadIdx.x;
    if (i >= n4) return;
    float4 t = reinterpret_cast<const float4*>(s)[i];
    t.x = __uint_as_float(f2tf(t.x));
    t.y = __uint_as_float(f2tf(t.y));
    t.z = __uint_as_float(f2tf(t.z));
    t.w = __uint_as_float(f2tf(t.w));
    reinterpret_cast<float4*>(d)[i] = t;
}

// ---------------- im2col -----------------------------------------------------
__global__ void k_im2col(const float* __restrict__ px) {
    int idx = blockIdx.x * blockDim.x + threadIdx.x;
    const int total = BB*NP*KC;
    if (idx >= total) return;
    int kc = idx % KC;  int bp = idx / KC;
    int p  = bp % NP;   int b  = bp / NP;
    int c  = kc / (PPP*PPP); int rem = kc % (PPP*PPP);
    int i  = rem / PPP, j = rem % PPP;
    int py = p / NPS,   pxi = p % NPS;
    int row = py*PPP + i, col = pxi*PPP + j;
    g_col[idx] = px[((size_t)(b*3 + c)*224 + row)*224 + col];
}

// ---------------- SIMT GEMM (patch-embed only, K=588, full fp32) ------------
#define TBM 64
#define TBN 64
#define TBK 16
__global__ void k_gemm(const float* __restrict__ A, const float* __restrict__ B,
                       float* __restrict__ C, int M, int N, int K) {
    __shared__ float As[TBK][TBM+4];
    __shared__ float Bs[TBK][TBN+4];
    int tid = threadIdx.x;
    int tx = tid & 15, ty = tid >> 4;
    int bm = blockIdx.y * TBM, bn = blockIdx.x * TBN;
    int lr = tid >> 2;
    int lc = (tid & 3) * 4;
    float acc[4][4] = {};

    for (int k0 = 0; k0 < K; k0 += TBK) {
        {
            int ar = bm + lr;
            if (ar < M && (k0 + lc + 3) < K) {
                float4 t = *reinterpret_cast<const float4*>(&A[(size_t)ar*K + k0 + lc]);
                As[lc+0][lr] = t.x; As[lc+1][lr] = t.y;
                As[lc+2][lr] = t.z; As[lc+3][lr] = t.w;
            } else {
                #pragma unroll
                for (int i = 0; i < 4; i++) {
                    int kk = k0 + lc + i;
                    As[lc+i][lr] = (ar < M && kk < K) ? A[(size_t)ar*K + kk] : 0.f;
                }
            }
        }
        {
            int br = bn + lr;
            if (br < N && (k0 + lc + 3) < K) {
                float4 t = *reinterpret_cast<const float4*>(&B[(size_t)br*K + k0 + lc]);
                Bs[lc+0][lr] = t.x; Bs[lc+1][lr] = t.y;
                Bs[lc+2][lr] = t.z; Bs[lc+3][lr] = t.w;
            } else {
                #pragma unroll
                for (int i = 0; i < 4; i++) {
                    int kk = k0 + lc + i;
                    Bs[lc+i][lr] = (br < N && kk < K) ? B[(size_t)br*K + kk] : 0.f;
                }
            }
        }
        __syncthreads();
        #pragma unroll
        for (int kk = 0; kk < TBK; kk++) {
            float a[4], b[4];
            #pragma unroll
            for (int i = 0; i < 4; i++) a[i] = As[kk][ty*4+i];
            #pragma unroll
            for (int j = 0; j < 4; j++) b[j] = Bs[kk][tx*4+j];
            #pragma unroll
            for (int i = 0; i < 4; i++)
                #pragma unroll
                for (int j = 0; j < 4; j++)
                    acc[i][j] += a[i] * b[j];
        }
        __syncthreads();
    }

    #pragma unroll
    for (int i = 0; i < 4; i++) {
        int r = bm + ty*4 + i;
        if (r >= M) continue;
        #pragma unroll
        for (int j = 0; j < 4; j++) {
            int c = bn + tx*4 + j;
            if (c >= N) continue;
            C[(size_t)r*N + c] = acc[i][j];
        }
    }
}

// ---------------- tf32 tensor-core GEMM with ldmatrix fragments --------------
// CTA 128x128, BK=16, 8 warps (2x4), warp tile 64x32. Inputs pre-rounded tf32.
#define PBM 128
#define PBN 128
#define PBK 16

__device__ __forceinline__ void cp_async16(void* smem, const void* gsrc, int bytes) {
    unsigned s = (unsigned)__cvta_generic_to_shared(smem);
    asm volatile("cp.async.cg.shared.global [%0], [%1], 16, %2;" :: "r"(s), "l"(gsrc), "r"(bytes));
}

__device__ __forceinline__ void ldsm_x4(unsigned r[4], unsigned saddr) {
    asm volatile("ldmatrix.sync.aligned.m8n8.x4.shared.b16 {%0,%1,%2,%3}, [%4];"
                 : "=r"(r[0]), "=r"(r[1]), "=r"(r[2]), "=r"(r[3]) : "r"(saddr));
}
__device__ __forceinline__ void ldsm_x2(unsigned r[2], unsigned saddr) {
    asm volatile("ldmatrix.sync.aligned.m8n8.x2.shared.b16 {%0,%1}, [%2];"
                 : "=r"(r[0]), "=r"(r[1]) : "r"(saddr));
}

__device__ __forceinline__ void mma_tf32(float c[4], const unsigned a[4], const unsigned b[2]) {
    asm volatile(
        "mma.sync.aligned.m16n8k8.row.col.f32.tf32.tf32.f32 "
        "{%0,%1,%2,%3}, {%4,%5,%6,%7}, {%8,%9}, {%0,%1,%2,%3};"
        : "+f"(c[0]), "+f"(c[1]), "+f"(c[2]), "+f"(c[3])
        : "r"(a[0]), "r"(a[1]), "r"(a[2]), "r"(a[3]), "r"(b[0]), "r"(b[1]));
}

// act bit0: quickGELU; act bit1: round output to tf32
__global__ void k_mma(const float* __restrict__ A, const float* __restrict__ B,
                      const float* __restrict__ bias, const float* __restrict__ add,
                      float* __restrict__ C, int M, int N, int K, int act) {
    __shared__ float sA[2][PBM*PBK];
    __shared__ float sB[2][PBN*PBK];
    int tid  = threadIdx.x;
    int lane = tid & 31, wid = tid >> 5;
    int wm = wid >> 2, wn = wid & 3;        // 2 x 4 warp grid
    int lg = lane >> 2, lt = lane & 3;      // quad group / thread-in-group
    int bm = blockIdx.y * PBM, bn = blockIdx.x * PBN;

    float c[4][4][4];
    #pragma unroll
    for (int i = 0; i < 4; i++)
        #pragma unroll
        for (int j = 0; j < 4; j++)
            #pragma unroll
            for (int r = 0; r < 4; r++) c[i][j][r] = 0.f;

    const int NIT = K / PBK;

    auto loadA = [&](int st, int k0) {
        #pragma unroll
        for (int t = 0; t < 2; t++) {
            int slot = tid + t*256;
            int r = slot >> 2, kc = slot & 3;
            int gr = bm + r;
            const float* src = A + (size_t)(gr < M ? gr : 0)*K + k0 + kc*4;
            int bytes = (gr < M) ? 16 : 0;
            float* dst = &sA[st][r*16 + ((kc ^ ((r>>1)&3)) << 2)];
            cp_async16(dst, src, bytes);
        }
    };
    auto loadB = [&](int st, int k0) {
        #pragma unroll
        for (int t = 0; t < 2; t++) {
            int slot = tid + t*256;
            int r = slot >> 2, kc = slot & 3;
            int gr = bn + r;
            const float* src = B + (size_t)gr*K + k0 + kc*4;
            float* dst = &sB[st][r*16 + ((kc ^ ((r>>1)&3)) << 2)];
            cp_async16(dst, src, 16);
        }
    };

    // ldmatrix lane-address precompute
    unsigned sAg = (unsigned)__cvta_generic_to_shared(&sA[0][0]);
    unsigned sBg = (unsigned)__cvta_generic_to_shared(&sB[0][0]);
    const unsigned stA = PBM*PBK*4;   // bytes per A stage
    const unsigned stB = PBN*PBK*4;
    int lr8 = lane & 7;
    int ami = lane >> 3;                        // 0..3 (A x4 matrix id)
    int arow = wm*64 + lr8 + ((ami & 1) << 3);  // row within CTA tile
    int asw  = (arow >> 1) & 3;
    int akg  = ami >> 1;                        // 0: k0-3, 1: k4-7
    unsigned aBase = sAg + (unsigned)arow*64u;  // 16 floats per row
    int bmi  = (lane >> 3) & 1;                 // B x2 matrix id (lanes 0-15 used)
    int brow = wn*32 + lr8;
    int bsw  = (brow >> 1) & 3;
    unsigned bBase = sBg + (unsigned)brow*64u;

    loadA(0, 0); loadB(0, 0);
    asm volatile("cp.async.commit_group;");

    for (int it = 0; it < NIT; it++) {
        int cur = it & 1;
        if (it + 1 < NIT) {
            loadA(cur ^ 1, (it+1)*PBK);
            loadB(cur ^ 1, (it+1)*PBK);
            asm volatile("cp.async.commit_group;");
            asm volatile("cp.async.wait_group 1;");
        } else {
            asm volatile("cp.async.wait_group 0;");
        }
        __syncthreads();

        unsigned aCur = aBase + cur*stA;
        unsigned bCur = bBase + cur*stB;
        #pragma unroll
        for (int ks = 0; ks < 2; ks++) {
            unsigned a[4][4], b[4][2];
            unsigned aoff = (unsigned)(((2*ks + akg) ^ asw) << 4);
            unsigned boff = (unsigned)(((2*ks + bmi) ^ bsw) << 4);
            #pragma unroll
            for (int mt = 0; mt < 4; mt++)
                ldsm_x4(a[mt], aCur + mt*1024u + aoff);
            #pragma unroll
            for (int nt = 0; nt < 4; nt++)
                ldsm_x2(b[nt], bCur + nt*512u + boff);
            #pragma unroll
            for (int mt = 0; mt < 4; mt++)
                #pragma unroll
                for (int nt = 0; nt < 4; nt++)
                    mma_tf32(c[mt][nt], a[mt], b[nt]);
        }
        __syncthreads();
    }

    // epilogue: bias -> act -> residual add -> (round) -> store (float2)
    #pragma unroll
    for (int nt = 0; nt < 4; nt++) {
        int cn = bn + wn*32 + nt*8 + lt*2;
        float bb0 = 0.f, bb1 = 0.f;
        if (bias) { bb0 = bias[cn]; bb1 = bias[cn+1]; }
        #pragma unroll
        for (int mt = 0; mt < 4; mt++) {
            #pragma unroll
            for (int h = 0; h < 2; h++) {
                int r = bm + wm*64 + mt*16 + lg + 8*h;
                if (r < M) {
                    float v0 = c[mt][nt][2*h+0] + bb0;
                    float v1 = c[mt][nt][2*h+1] + bb1;
                    if (act & 1) {
                        v0 = v0 / (1.f + __expf(-1.702f * v0));
                        v1 = v1 / (1.f + __expf(-1.702f * v1));
                    }
                    if (add) {
                        float2 t = *reinterpret_cast<const float2*>(&add[(size_t)r*N + cn]);
                        v0 += t.x; v1 += t.y;
                    }
                    if (act & 2) {
                        v0 = __uint_as_float(f2tf(v0));
                        v1 = __uint_as_float(f2tf(v1));
                    }
                    *reinterpret_cast<float2*>(&C[(size_t)r*N + cn]) = make_float2(v0, v1);
                }
            }
        }
    }
}

// ---------------- assemble embeddings ----------------------------------------
__global__ void k_assemble(const float* __restrict__ cls,
                           const float* __restrict__ pos,
                           float* __restrict__ x) {
    int idx = blockIdx.x * blockDim.x + threadIdx.x;
    if (idx >= MM*DD) return;
    int d = idx % DD; int bs = idx / DD;
    int s = bs % SS;  int b = bs / SS;
    float v = (s == 0) ? cls[d] : g_feat[((size_t)(b*NP + s - 1))*DD + d];
    x[idx] = v + pos[(size_t)s*DD + d];
}

// ---------------- LayerNorm (output rounded to tf32 for GEMM consumption) ----
__global__ void k_ln(const float* __restrict__ x, const float* __restrict__ w,
                     const float* __restrict__ b, float* __restrict__ out) {
    int row = blockIdx.x;
    const float* xr = x + (size_t)row*DD;
    __shared__ float red[256];
    int t = threadIdx.x;
    float s = 0.f;
    for (int i = t; i < DD; i += 256) s += xr[i];
    red[t] = s; __syncthreads();
    for (int st = 128; st > 0; st >>= 1) { if (t < st) red[t] += red[t+st]; __syncthreads(); }
    float mean = red[0] * (1.f/DD);
    __syncthreads();
    float vs = 0.f;
    for (int i = t; i < DD; i += 256) { float d = xr[i]-mean; vs += d*d; }
    red[t] = vs; __syncthreads();
    for (int st = 128; st > 0; st >>= 1) { if (t < st) red[t] += red[t+st]; __syncthreads(); }
    float rstd = rsqrtf(red[0] * (1.f/DD) + LNEPS);
    float* o = out + (size_t)row*DD;
    for (int i = t; i < DD; i += 256)
        o[i] = __uint_as_float(f2tf((xr[i]-mean)*rstd*w[i] + b[i]));
}

// ---------------- attention scores -------------------------------------------
__global__ void k_scores(const float* __restrict__ Q, const float* __restrict__ Kt) {
    int bh = blockIdx.z;
    int b = bh / HH, h = bh % HH;
    int q0 = blockIdx.y * 16, k0 = blockIdx.x * 16;
    __shared__ float Qs[16][DHH+1];
    __shared__ float Ks[16][DHH+1];
    int tid = threadIdx.y*16 + threadIdx.x;
    int lr = tid >> 4;
    int lc = (tid & 15) * 4;
    {
        int qr = q0 + lr;
        if (qr < SS) {
            float4 t = *reinterpret_cast<const float4*>(&Q[((size_t)(b*SS+qr))*DD + h*DHH + lc]);
            Qs[lr][lc]=t.x; Qs[lr][lc+1]=t.y; Qs[lr][lc+2]=t.z; Qs[lr][lc+3]=t.w;
        } else { Qs[lr][lc]=Qs[lr][lc+1]=Qs[lr][lc+2]=Qs[lr][lc+3]=0.f; }
        int kr = k0 + lr;
        if (kr < SS) {
            float4 t = *reinterpret_cast<const float4*>(&Kt[((size_t)(b*SS+kr))*DD + h*DHH + lc]);
            Ks[lr][lc]=t.x; Ks[lr][lc+1]=t.y; Ks[lr][lc+2]=t.z; Ks[lr][lc+3]=t.w;
        } else { Ks[lr][lc]=Ks[lr][lc+1]=Ks[lr][lc+2]=Ks[lr][lc+3]=0.f; }
    }
    __syncthreads();
    int q = q0 + threadIdx.y, k = k0 + threadIdx.x;
    if (q < SS && k < SS) {
        float acc = 0.f;
        #pragma unroll
        for (int d = 0; d < DHH; d++) acc += Qs[threadIdx.y][d] * Ks[threadIdx.x][d];
        g_att[((size_t)bh*SS + q)*SS + k] = acc * 0.125f;
    }
}

// ---------------- softmax -----------------------------------------------------
__global__ void k_softmax() {
    size_t row = blockIdx.x;
    float* p = g_att + row * (size_t)SS;
    int t = threadIdx.x;
    float a = p[t];
    float extra = (t == 0) ? p[256] : -1e30f;
    __shared__ float red[256];
    float m = fmaxf(a, extra);
    red[t] = m; __syncthreads();
    for (int st = 128; st > 0; st >>= 1) { if (t < st) red[t] = fmaxf(red[t], red[t+st]); __syncthreads(); }
    m = red[0];
    __syncthreads();
    float ea = __expf(a - m);
    float eb = (t == 0) ? __expf(extra - m) : 0.f;
    red[t] = ea + eb; __syncthreads();
    for (int st = 128; st > 0; st >>= 1) { if (t < st) red[t] += red[t+st]; __syncthreads(); }
    float inv = 1.f / red[0];
    p[t] = ea * inv;
    if (t == 0) p[256] = eb * inv;
}

// ---------------- ctx = attn @ V (output rounded to tf32) --------------------
__global__ void k_ctx(const float* __restrict__ V, float* __restrict__ Ctx) {
    int bh = blockIdx.y; int b = bh / HH, h = bh % HH;
    int q0 = blockIdx.x * 16;
    int tx = threadIdx.x, ty = threadIdx.y;
    int tid = ty*16 + tx;
    __shared__ float As[16][17];
    __shared__ float Vs[16][DHH];
    const float* att = g_att + (size_t)bh*SS*SS;
    float acc[4] = {0.f, 0.f, 0.f, 0.f};
    int vlr = tid >> 4, vlc = (tid & 15) * 4;
    for (int k0 = 0; k0 < SS; k0 += 16) {
        int q = q0 + ty, kk_ = k0 + tx;
        As[ty][tx] = (q < SS && kk_ < SS) ? att[(size_t)q*SS + kk_] : 0.f;
        int kv = k0 + vlr;
        if (kv < SS) {
            float4 t4 = *reinterpret_cast<const float4*>(&V[((size_t)(b*SS+kv))*DD + h*DHH + vlc]);
            Vs[vlr][vlc]=t4.x; Vs[vlr][vlc+1]=t4.y; Vs[vlr][vlc+2]=t4.z; Vs[vlr][vlc+3]=t4.w;
        } else {
            Vs[vlr][vlc]=Vs[vlr][vlc+1]=Vs[vlr][vlc+2]=Vs[vlr][vlc+3]=0.f;
        }
        __syncthreads();
        #pragma unroll
        for (int kk = 0; kk < 16; kk++) {
            float a = As[ty][kk];
            #pragma unroll
            for (int j = 0; j < 4; j++) acc[j] += a * Vs[kk][tx + 16*j];
        }
        __syncthreads();
    }
    int q = q0 + ty;
    if (q < SS) {
        size_t base = ((size_t)(b*SS+q))*DD + h*DHH;
        #pragma unroll
        for (int j = 0; j < 4; j++)
            Ctx[base + tx + 16*j] = __uint_as_float(f2tf(acc[j]));
    }
}

// ---------------- host orchestration ------------------------------------------
extern "C" void kernel_launch(void* const* d_in, const int* in_sizes, int n_in,
                              void* d_out, int out_size) {
    const float* pixel    = (const float*)d_in[0];
    const float* patch_w  = (const float*)d_in[1];
    const float* class_e  = (const float*)d_in[2];
    const float* pos_e    = (const float*)d_in[3];
    const float* ln1_w    = (const float*)d_in[4];
    const float* ln1_b    = (const float*)d_in[5];
    const float* q_w      = (const float*)d_in[6];
    const float* q_b      = (const float*)d_in[7];
    const float* k_w      = (const float*)d_in[8];
    const float* k_b      = (const float*)d_in[9];
    const float* v_w      = (const float*)d_in[10];
    const float* v_b      = (const float*)d_in[11];
    const float* o_w      = (const float*)d_in[12];
    const float* o_b      = (const float*)d_in[13];
    const float* ln2_w    = (const float*)d_in[14];
    const float* ln2_b    = (const float*)d_in[15];
    const float* fc1_w    = (const float*)d_in[16];
    const float* fc1_b    = (const float*)d_in[17];
    const float* fc2_w    = (const float*)d_in[18];
    const float* fc2_b    = (const float*)d_in[19];
    float* x = (float*)d_out;

    float *col, *feat, *h, *q, *k, *v, *ctx, *ff;
    float *wq, *wk, *wv, *wo, *wf1, *wf2;
    cudaGetSymbolAddress((void**)&col,  g_col);
    cudaGetSymbolAddress((void**)&feat, g_feat);
    cudaGetSymbolAddress((void**)&h,    g_h);
    cudaGetSymbolAddress((void**)&q,    g_q);
    cudaGetSymbolAddress((void**)&k,    g_k);
    cudaGetSymbolAddress((void**)&v,    g_v);
    cudaGetSymbolAddress((void**)&ctx,  g_ctx);
    cudaGetSymbolAddress((void**)&ff,   g_ff);
    cudaGetSymbolAddress((void**)&wq,   g_wq);
    cudaGetSymbolAddress((void**)&wk,   g_wk);
    cudaGetSymbolAddress((void**)&wv,   g_wv);
    cudaGetSymbolAddress((void**)&wo,   g_wo);
    cudaGetSymbolAddress((void**)&wf1,  g_wf1);
    cudaGetSymbolAddress((void**)&wf2,  g_wf2);

    // --- pre-round weights to tf32 ---
    const int nQ = LLN*DD*DD/4;            // float4 count
    const int nF = LLN*FFD*DD/4;
    k_round<<<(nQ+255)/256, 256>>>(q_w,  wq,  nQ);
    k_round<<<(nQ+255)/256, 256>>>(k_w,  wk,  nQ);
    k_round<<<(nQ+255)/256, 256>>>(v_w,  wv,  nQ);
    k_round<<<(nQ+255)/256, 256>>>(o_w,  wo,  nQ);
    k_round<<<(nF+255)/256, 256>>>(fc1_w, wf1, nF);
    k_round<<<(nF+255)/256, 256>>>(fc2_w, wf2, nF);

    // --- embeddings ---
    k_im2col<<<(BB*NP*KC + 255)/256, 256>>>(pixel);
    k_gemm<<<dim3(DD/TBN, (BB*NP + TBM-1)/TBM), 256>>>(col, patch_w, feat, BB*NP, DD, KC);
    k_assemble<<<(MM*DD + 255)/256, 256>>>(class_e, pos_e, x);

    dim3 gD (DD/PBN,  (MM + PBM-1)/PBM);    // (8, 33)
    dim3 gFF(FFD/PBN, (MM + PBM-1)/PBM);    // (32, 33)

    for (int l = 0; l < LLN; l++) {
        const float* qw = wq + (size_t)l*DD*DD;   const float* qb = q_b + (size_t)l*DD;
        const float* kw = wk + (size_t)l*DD*DD;   const float* kb = k_b + (size_t)l*DD;
        const float* vw = wv + (size_t)l*DD*DD;   const float* vb = v_b + (size_t)l*DD;
        const float* ow = wo + (size_t)l*DD*DD;   const float* ob = o_b + (size_t)l*DD;
        const float* f1w = wf1 + (size_t)l*FFD*DD; const float* f1b = fc1_b + (size_t)l*FFD;
        const float* f2w = wf2 + (size_t)l*FFD*DD; const float* f2b = fc2_b + (size_t)l*DD;

        // attention block
        k_ln<<<MM, 256>>>(x, ln1_w + (size_t)l*DD, ln1_b + (size_t)l*DD, h);
        k_mma<<<gD, 256>>>(h, qw, qb, nullptr, q, MM, DD, DD, 0);
        k_mma<<<gD, 256>>>(h, kw, kb, nullptr, k, MM, DD, DD, 0);
        k_mma<<<gD, 256>>>(h, vw, vb, nullptr, v, MM, DD, DD, 0);
        k_scores<<<dim3(17, 17, BB*HH), dim3(16,16)>>>(q, k);
        k_softmax<<<BB*HH*SS, 256>>>();
        k_ctx<<<dim3(17, BB*HH), dim3(16,16)>>>(v, ctx);
        k_mma<<<gD, 256>>>(ctx, ow, ob, x, x, MM, DD, DD, 0);    // +residual

        // MLP block
        k_ln<<<MM, 256>>>(x, ln2_w + (size_t)l*DD, ln2_b + (size_t)l*DD, h);
        k_mma<<<gFF, 256>>>(h, f1w, f1b, nullptr, ff, MM, FFD, DD, 3);   // gelu + round
        k_mma<<<gD, 256>>>(ff, f2w, f2b, x, x, MM, DD, FFD, 0);          // +residual

        // MoD top-k block: identity -> skipped
    }
    (void)in_sizes; (void)n_in; (void)out_size;
}

// round 10
// speedup vs baseline: 1.4929x; 1.4929x over previous
#include <cuda_runtime.h>
#include <cuda_fp16.h>
#include <math.h>

// Problem constants
#define BB   16
#define SS   257
#define DD   1024
#define HH   16
#define DHH  64
#define FFD  4096
#define LLN  6
#define PPP  14
#define NPS  16
#define NP   256
#define KC   (3*14*14)   // 588 im2col K
#define MM   (BB*SS)     // 4112 rows
#define LNEPS 1e-5f

// ---------------- scratch ----------------------------------------------------
__device__ float  g_col [BB*NP*KC];
__device__ float  g_feat[BB*NP*DD];
__device__ __half g_h   [MM*DD];                 // LN output (fp16)
__device__ float  g_q   [MM*DD];
__device__ float  g_k   [MM*DD];
__device__ float  g_v   [MM*DD];
__device__ __half g_ctx [MM*DD];                 // attention context (fp16)
__device__ float  g_att [(size_t)BB*HH*SS*SS];
__device__ __half g_ff  [(size_t)MM*FFD];        // MLP hidden (fp16)
// fp16 weights
__device__ __half g_hq [LLN*DD*DD];
__device__ __half g_hk [LLN*DD*DD];
__device__ __half g_hv [LLN*DD*DD];
__device__ __half g_ho [LLN*DD*DD];
__device__ __half g_hf1[(size_t)LLN*FFD*DD];
__device__ __half g_hf2[(size_t)LLN*FFD*DD];

// ---------------- fp32 -> fp16 convert ---------------------------------------
__global__ void k_half(const float* __restrict__ s, __half* __restrict__ d, int n4) {
    int i = blockIdx.x * blockDim.x + threadIdx.x;
    if (i >= n4) return;
    float4 t = reinterpret_cast<const float4*>(s)[i];
    __half2* d2 = reinterpret_cast<__half2*>(d);
    d2[2*i+0] = __floats2half2_rn(t.x, t.y);
    d2[2*i+1] = __floats2half2_rn(t.z, t.w);
}

// ---------------- im2col -----------------------------------------------------
__global__ void k_im2col(const float* __restrict__ px) {
    int idx = blockIdx.x * blockDim.x + threadIdx.x;
    const int total = BB*NP*KC;
    if (idx >= total) return;
    int kc = idx % KC;  int bp = idx / KC;
    int p  = bp % NP;   int b  = bp / NP;
    int c  = kc / (PPP*PPP); int rem = kc % (PPP*PPP);
    int i  = rem / PPP, j = rem % PPP;
    int py = p / NPS,   pxi = p % NPS;
    int row = py*PPP + i, col = pxi*PPP + j;
    g_col[idx] = px[((size_t)(b*3 + c)*224 + row)*224 + col];
}

// ---------------- SIMT GEMM (patch-embed only, K=588, full fp32) ------------
#define TBM 64
#define TBN 64
#define TBK 16
__global__ void k_gemm(const float* __restrict__ A, const float* __restrict__ B,
                       float* __restrict__ C, int M, int N, int K) {
    __shared__ float As[TBK][TBM+4];
    __shared__ float Bs[TBK][TBN+4];
    int tid = threadIdx.x;
    int tx = tid & 15, ty = tid >> 4;
    int bm = blockIdx.y * TBM, bn = blockIdx.x * TBN;
    int lr = tid >> 2;
    int lc = (tid & 3) * 4;
    float acc[4][4] = {};

    for (int k0 = 0; k0 < K; k0 += TBK) {
        {
            int ar = bm + lr;
            if (ar < M && (k0 + lc + 3) < K) {
                float4 t = *reinterpret_cast<const float4*>(&A[(size_t)ar*K + k0 + lc]);
                As[lc+0][lr] = t.x; As[lc+1][lr] = t.y;
                As[lc+2][lr] = t.z; As[lc+3][lr] = t.w;
            } else {
                #pragma unroll
                for (int i = 0; i < 4; i++) {
                    int kk = k0 + lc + i;
                    As[lc+i][lr] = (ar < M && kk < K) ? A[(size_t)ar*K + kk] : 0.f;
                }
            }
        }
        {
            int br = bn + lr;
            if (br < N && (k0 + lc + 3) < K) {
                float4 t = *reinterpret_cast<const float4*>(&B[(size_t)br*K + k0 + lc]);
                Bs[lc+0][lr] = t.x; Bs[lc+1][lr] = t.y;
                Bs[lc+2][lr] = t.z; Bs[lc+3][lr] = t.w;
            } else {
                #pragma unroll
                for (int i = 0; i < 4; i++) {
                    int kk = k0 + lc + i;
                    Bs[lc+i][lr] = (br < N && kk < K) ? B[(size_t)br*K + kk] : 0.f;
                }
            }
        }
        __syncthreads();
        #pragma unroll
        for (int kk = 0; kk < TBK; kk++) {
            float a[4], b[4];
            #pragma unroll
            for (int i = 0; i < 4; i++) a[i] = As[kk][ty*4+i];
            #pragma unroll
            for (int j = 0; j < 4; j++) b[j] = Bs[kk][tx*4+j];
            #pragma unroll
            for (int i = 0; i < 4; i++)
                #pragma unroll
                for (int j = 0; j < 4; j++)
                    acc[i][j] += a[i] * b[j];
        }
        __syncthreads();
    }

    #pragma unroll
    for (int i = 0; i < 4; i++) {
        int r = bm + ty*4 + i;
        if (r >= M) continue;
        #pragma unroll
        for (int j = 0; j < 4; j++) {
            int c = bn + tx*4 + j;
            if (c >= N) continue;
            C[(size_t)r*N + c] = acc[i][j];
        }
    }
}

// ================ fp16 tensor-core GEMM: C = A[M,K] * B[N,K]^T ===============
// CTA 128x128, BK=64 halves (128B rows), 8 warps (2x4), warp tile 64x32,
// m16n8k16 f16 MMA with fp32 accum, ldmatrix fragments, cp.async 2-stage.
#define HBM 128
#define HBN 128
#define HBK 64
#define HST 16384          // bytes per (A or B) stage
#define HSMEM (4*HST)      // 64 KB dynamic

__device__ __forceinline__ void cpa16(unsigned saddr, const void* gsrc, int bytes) {
    asm volatile("cp.async.cg.shared.global [%0], [%1], 16, %2;"
                 :: "r"(saddr), "l"(gsrc), "r"(bytes));
}
__device__ __forceinline__ void ldsm4(unsigned r[4], unsigned saddr) {
    asm volatile("ldmatrix.sync.aligned.m8n8.x4.shared.b16 {%0,%1,%2,%3}, [%4];"
                 : "=r"(r[0]), "=r"(r[1]), "=r"(r[2]), "=r"(r[3]) : "r"(saddr));
}
__device__ __forceinline__ void mma_f16(float c[4], const unsigned a[4],
                                        unsigned b0, unsigned b1) {
    asm volatile(
        "mma.sync.aligned.m16n8k16.row.col.f32.f16.f16.f32 "
        "{%0,%1,%2,%3}, {%4,%5,%6,%7}, {%8,%9}, {%0,%1,%2,%3};"
        : "+f"(c[0]), "+f"(c[1]), "+f"(c[2]), "+f"(c[3])
        : "r"(a[0]), "r"(a[1]), "r"(a[2]), "r"(a[3]), "r"(b0), "r"(b1));
}

// act bit0: quickGELU; act bit1: store fp16 (else fp32)
__global__ void __launch_bounds__(256)
k_hmma(const __half* __restrict__ A, const __half* __restrict__ B,
       const float* __restrict__ bias, const float* __restrict__ add,
       void* __restrict__ Cv, int M, int N, int K, int act) {
    extern __shared__ char hsm[];
    unsigned base = (unsigned)__cvta_generic_to_shared(hsm);
    int tid = threadIdx.x;
    int lane = tid & 31, w = tid >> 5;
    int wm = w >> 2, wn = w & 3;            // 2x4 warp grid
    int lg = lane >> 2, lt = lane & 3;
    int lr8 = lane & 7;
    int bm = blockIdx.y * HBM, bn = blockIdx.x * HBN;

    float c[4][4][4];
    #pragma unroll
    for (int i = 0; i < 4; i++)
        #pragma unroll
        for (int j = 0; j < 4; j++)
            #pragma unroll
            for (int r = 0; r < 4; r++) c[i][j][r] = 0.f;

    const int NIT = K / HBK;

    // stage loaders: 1024 16B-chunks per tile, 4 per thread
    auto loadA = [&](int st, int k0) {
        #pragma unroll
        for (int t = 0; t < 4; t++) {
            int slot = tid + t*256;
            int r = slot >> 3, ch = slot & 7;
            int gr = bm + r;
            const __half* src = A + (size_t)(gr < M ? gr : 0)*K + k0 + ch*8;
            cpa16(base + st*HST + r*128u + (unsigned)((ch ^ (r & 7)) << 4),
                  src, (gr < M) ? 16 : 0);
        }
    };
    auto loadB = [&](int st, int k0) {
        #pragma unroll
        for (int t = 0; t < 4; t++) {
            int slot = tid + t*256;
            int r = slot >> 3, ch = slot & 7;
            const __half* src = B + (size_t)(bn + r)*K + k0 + ch*8;
            cpa16(base + 2*HST + st*HST + r*128u + (unsigned)((ch ^ (r & 7)) << 4),
                  src, 16);
        }
    };

    // ldmatrix per-lane address components
    int agrp = lane >> 3;                      // 0..3
    int arow = ((agrp & 1) << 3) + lr8;        // row offset within m16 tile
    int akc  = agrp >> 1;                      // chunk offset (k half)
    int brow = ((lane >> 4) << 3) + lr8;       // row offset within n16 pair
    int bkc  = (lane >> 3) & 1;

    loadA(0, 0); loadB(0, 0);
    asm volatile("cp.async.commit_group;");

    for (int it = 0; it < NIT; it++) {
        int cur = it & 1;
        if (it + 1 < NIT) {
            loadA(cur ^ 1, (it+1)*HBK);
            loadB(cur ^ 1, (it+1)*HBK);
            asm volatile("cp.async.commit_group;");
            asm volatile("cp.async.wait_group 1;");
        } else {
            asm volatile("cp.async.wait_group 0;");
        }
        __syncthreads();

        unsigned aB = base + cur*HST;
        unsigned bB = base + 2*HST + cur*HST;
        #pragma unroll
        for (int ks = 0; ks < 4; ks++) {
            unsigned a[4][4], bf[2][4];
            #pragma unroll
            for (int mt = 0; mt < 4; mt++) {
                int row = wm*64 + mt*16 + arow;
                ldsm4(a[mt], aB + (unsigned)row*128u
                              + (unsigned)(((2*ks + akc) ^ lr8) << 4));
            }
            #pragma unroll
            for (int p = 0; p < 2; p++) {
                int row = wn*32 + p*16 + brow;
                ldsm4(bf[p], bB + (unsigned)row*128u
                              + (unsigned)(((2*ks + bkc) ^ lr8) << 4));
            }
            #pragma unroll
            for (int mt = 0; mt < 4; mt++)
                #pragma unroll
                for (int nt = 0; nt < 4; nt++)
                    mma_f16(c[mt][nt], a[mt],
                            bf[nt >> 1][2*(nt & 1)], bf[nt >> 1][2*(nt & 1) + 1]);
        }
        __syncthreads();
    }

    // epilogue: bias -> gelu -> residual -> store (fp32 or fp16)
    #pragma unroll
    for (int nt = 0; nt < 4; nt++) {
        int cn = bn + wn*32 + nt*8 + lt*2;
        float bb0 = 0.f, bb1 = 0.f;
        if (bias) { bb0 = bias[cn]; bb1 = bias[cn+1]; }
        #pragma unroll
        for (int mt = 0; mt < 4; mt++) {
            #pragma unroll
            for (int h = 0; h < 2; h++) {
                int r = bm + wm*64 + mt*16 + lg + 8*h;
                if (r < M) {
                    float v0 = c[mt][nt][2*h+0] + bb0;
                    float v1 = c[mt][nt][2*h+1] + bb1;
                    if (act & 1) {
                        v0 = v0 / (1.f + __expf(-1.702f * v0));
                        v1 = v1 / (1.f + __expf(-1.702f * v1));
                    }
                    if (add) {
                        float2 t = *reinterpret_cast<const float2*>(&add[(size_t)r*N + cn]);
                        v0 += t.x; v1 += t.y;
                    }
                    if (act & 2) {
                        __half* Ch = (__half*)Cv;
                        *reinterpret_cast<__half2*>(&Ch[(size_t)r*N + cn]) =
                            __floats2half2_rn(v0, v1);
                    } else {
                        float* Cf = (float*)Cv;
                        *reinterpret_cast<float2*>(&Cf[(size_t)r*N + cn]) =
                            make_float2(v0, v1);
                    }
                }
            }
        }
    }
}

// ---------------- assemble embeddings ----------------------------------------
__global__ void k_assemble(const float* __restrict__ cls,
                           const float* __restrict__ pos,
                           float* __restrict__ x) {
    int idx = blockIdx.x * blockDim.x + threadIdx.x;
    if (idx >= MM*DD) return;
    int d = idx % DD; int bs = idx / DD;
    int s = bs % SS;  int b = bs / SS;
    float v = (s == 0) ? cls[d] : g_feat[((size_t)(b*NP + s - 1))*DD + d];
    x[idx] = v + pos[(size_t)s*DD + d];
}

// ---------------- LayerNorm (fp16 output for GEMM consumption) ---------------
__global__ void k_ln(const float* __restrict__ x, const float* __restrict__ w,
                     const float* __restrict__ b, __half* __restrict__ out) {
    int row = blockIdx.x;
    const float* xr = x + (size_t)row*DD;
    __shared__ float red[256];
    int t = threadIdx.x;
    float s = 0.f;
    for (int i = t; i < DD; i += 256) s += xr[i];
    red[t] = s; __syncthreads();
    for (int st = 128; st > 0; st >>= 1) { if (t < st) red[t] += red[t+st]; __syncthreads(); }
    float mean = red[0] * (1.f/DD);
    __syncthreads();
    float vs = 0.f;
    for (int i = t; i < DD; i += 256) { float d = xr[i]-mean; vs += d*d; }
    red[t] = vs; __syncthreads();
    for (int st = 128; st > 0; st >>= 1) { if (t < st) red[t] += red[t+st]; __syncthreads(); }
    float rstd = rsqrtf(red[0] * (1.f/DD) + LNEPS);
    __half* o = out + (size_t)row*DD;
    for (int i = t; i < DD; i += 256)
        o[i] = __float2half_rn((xr[i]-mean)*rstd*w[i] + b[i]);
}

// ---------------- attention scores -------------------------------------------
__global__ void k_scores(const float* __restrict__ Q, const float* __restrict__ Kt) {
    int bh = blockIdx.z;
    int b = bh / HH, h = bh % HH;
    int q0 = blockIdx.y * 16, k0 = blockIdx.x * 16;
    __shared__ float Qs[16][DHH+1];
    __shared__ float Ks[16][DHH+1];
    int tid = threadIdx.y*16 + threadIdx.x;
    int lr = tid >> 4;
    int lc = (tid & 15) * 4;
    {
        int qr = q0 + lr;
        if (qr < SS) {
            float4 t = *reinterpret_cast<const float4*>(&Q[((size_t)(b*SS+qr))*DD + h*DHH + lc]);
            Qs[lr][lc]=t.x; Qs[lr][lc+1]=t.y; Qs[lr][lc+2]=t.z; Qs[lr][lc+3]=t.w;
        } else { Qs[lr][lc]=Qs[lr][lc+1]=Qs[lr][lc+2]=Qs[lr][lc+3]=0.f; }
        int kr = k0 + lr;
        if (kr < SS) {
            float4 t = *reinterpret_cast<const float4*>(&Kt[((size_t)(b*SS+kr))*DD + h*DHH + lc]);
            Ks[lr][lc]=t.x; Ks[lr][lc+1]=t.y; Ks[lr][lc+2]=t.z; Ks[lr][lc+3]=t.w;
        } else { Ks[lr][lc]=Ks[lr][lc+1]=Ks[lr][lc+2]=Ks[lr][lc+3]=0.f; }
    }
    __syncthreads();
    int q = q0 + threadIdx.y, k = k0 + threadIdx.x;
    if (q < SS && k < SS) {
        float acc = 0.f;
        #pragma unroll
        for (int d = 0; d < DHH; d++) acc += Qs[threadIdx.y][d] * Ks[threadIdx.x][d];
        g_att[((size_t)bh*SS + q)*SS + k] = acc * 0.125f;
    }
}

// ---------------- softmax -----------------------------------------------------
__global__ void k_softmax() {
    size_t row = blockIdx.x;
    float* p = g_att + row * (size_t)SS;
    int t = threadIdx.x;
    float a = p[t];
    float extra = (t == 0) ? p[256] : -1e30f;
    __shared__ float red[256];
    float m = fmaxf(a, extra);
    red[t] = m; __syncthreads();
    for (int st = 128; st > 0; st >>= 1) { if (t < st) red[t] = fmaxf(red[t], red[t+st]); __syncthreads(); }
    m = red[0];
    __syncthreads();
    float ea = __expf(a - m);
    float eb = (t == 0) ? __expf(extra - m) : 0.f;
    red[t] = ea + eb; __syncthreads();
    for (int st = 128; st > 0; st >>= 1) { if (t < st) red[t] += red[t+st]; __syncthreads(); }
    float inv = 1.f / red[0];
    p[t] = ea * inv;
    if (t == 0) p[256] = eb * inv;
}

// ---------------- ctx = attn @ V (fp16 output) --------------------------------
__global__ void k_ctx(const float* __restrict__ V, __half* __restrict__ Ctx) {
    int bh = blockIdx.y; int b = bh / HH, h = bh % HH;
    int q0 = blockIdx.x * 16;
    int tx = threadIdx.x, ty = threadIdx.y;
    int tid = ty*16 + tx;
    __shared__ float As[16][17];
    __shared__ float Vs[16][DHH];
    const float* att = g_att + (size_t)bh*SS*SS;
    float acc[4] = {0.f, 0.f, 0.f, 0.f};
    int vlr = tid >> 4, vlc = (tid & 15) * 4;
    for (int k0 = 0; k0 < SS; k0 += 16) {
        int q = q0 + ty, kk_ = k0 + tx;
        As[ty][tx] = (q < SS && kk_ < SS) ? att[(size_t)q*SS + kk_] : 0.f;
        int kv = k0 + vlr;
        if (kv < SS) {
            float4 t4 = *reinterpret_cast<const float4*>(&V[((size_t)(b*SS+kv))*DD + h*DHH + vlc]);
            Vs[vlr][vlc]=t4.x; Vs[vlr][vlc+1]=t4.y; Vs[vlr][vlc+2]=t4.z; Vs[vlr][vlc+3]=t4.w;
        } else {
            Vs[vlr][vlc]=Vs[vlr][vlc+1]=Vs[vlr][vlc+2]=Vs[vlr][vlc+3]=0.f;
        }
        __syncthreads();
        #pragma unroll
        for (int kk = 0; kk < 16; kk++) {
            float a = As[ty][kk];
            #pragma unroll
            for (int j = 0; j < 4; j++) acc[j] += a * Vs[kk][tx + 16*j];
        }
        __syncthreads();
    }
    int q = q0 + ty;
    if (q < SS) {
        size_t base = ((size_t)(b*SS+q))*DD + h*DHH;
        #pragma unroll
        for (int j = 0; j < 4; j++)
            Ctx[base + tx + 16*j] = __float2half_rn(acc[j]);
    }
}

// ---------------- host orchestration ------------------------------------------
extern "C" void kernel_launch(void* const* d_in, const int* in_sizes, int n_in,
                              void* d_out, int out_size) {
    const float* pixel    = (const float*)d_in[0];
    const float* patch_w  = (const float*)d_in[1];
    const float* class_e  = (const float*)d_in[2];
    const float* pos_e    = (const float*)d_in[3];
    const float* ln1_w    = (const float*)d_in[4];
    const float* ln1_b    = (const float*)d_in[5];
    const float* q_w      = (const float*)d_in[6];
    const float* q_b      = (const float*)d_in[7];
    const float* k_w      = (const float*)d_in[8];
    const float* k_b      = (const float*)d_in[9];
    const float* v_w      = (const float*)d_in[10];
    const float* v_b      = (const float*)d_in[11];
    const float* o_w      = (const float*)d_in[12];
    const float* o_b      = (const float*)d_in[13];
    const float* ln2_w    = (const float*)d_in[14];
    const float* ln2_b    = (const float*)d_in[15];
    const float* fc1_w    = (const float*)d_in[16];
    const float* fc1_b    = (const float*)d_in[17];
    const float* fc2_w    = (const float*)d_in[18];
    const float* fc2_b    = (const float*)d_in[19];
    float* x = (float*)d_out;

    float *col, *feat, *q, *k, *v;
    __half *h, *ctx, *ff, *hq, *hk, *hv, *ho, *hf1, *hf2;
    cudaGetSymbolAddress((void**)&col,  g_col);
    cudaGetSymbolAddress((void**)&feat, g_feat);
    cudaGetSymbolAddress((void**)&h,    g_h);
    cudaGetSymbolAddress((void**)&q,    g_q);
    cudaGetSymbolAddress((void**)&k,    g_k);
    cudaGetSymbolAddress((void**)&v,    g_v);
    cudaGetSymbolAddress((void**)&ctx,  g_ctx);
    cudaGetSymbolAddress((void**)&ff,   g_ff);
    cudaGetSymbolAddress((void**)&hq,   g_hq);
    cudaGetSymbolAddress((void**)&hk,   g_hk);
    cudaGetSymbolAddress((void**)&hv,   g_hv);
    cudaGetSymbolAddress((void**)&ho,   g_ho);
    cudaGetSymbolAddress((void**)&hf1,  g_hf1);
    cudaGetSymbolAddress((void**)&hf2,  g_hf2);

    cudaFuncSetAttribute(k_hmma, cudaFuncAttributeMaxDynamicSharedMemorySize, HSMEM);

    // --- convert weights to fp16 (once per launch; deterministic) ---
    const int nQ = LLN*DD*DD/4;
    const int nF = LLN*FFD*DD/4;
    k_half<<<(nQ+255)/256, 256>>>(q_w,  hq,  nQ);
    k_half<<<(nQ+255)/256, 256>>>(k_w,  hk,  nQ);
    k_half<<<(nQ+255)/256, 256>>>(v_w,  hv,  nQ);
    k_half<<<(nQ+255)/256, 256>>>(o_w,  ho,  nQ);
    k_half<<<(nF+255)/256, 256>>>(fc1_w, hf1, nF);
    k_half<<<(nF+255)/256, 256>>>(fc2_w, hf2, nF);

    // --- embeddings ---
    k_im2col<<<(BB*NP*KC + 255)/256, 256>>>(pixel);
    k_gemm<<<dim3(DD/TBN, (BB*NP + TBM-1)/TBM), 256>>>(col, patch_w, feat, BB*NP, DD, KC);
    k_assemble<<<(MM*DD + 255)/256, 256>>>(class_e, pos_e, x);

    dim3 gD (DD/HBN,  (MM + HBM-1)/HBM);    // (8, 33)
    dim3 gFF(FFD/HBN, (MM + HBM-1)/HBM);    // (32, 33)

    for (int l = 0; l < LLN; l++) {
        const __half* qw = hq + (size_t)l*DD*DD;   const float* qb = q_b + (size_t)l*DD;
        const __half* kw = hk + (size_t)l*DD*DD;   const float* kb = k_b + (size_t)l*DD;
        const __half* vw = hv + (size_t)l*DD*DD;   const float* vb = v_b + (size_t)l*DD;
        const __half* ow = ho + (size_t)l*DD*DD;   const float* ob = o_b + (size_t)l*DD;
        const __half* f1w = hf1 + (size_t)l*FFD*DD; const float* f1b = fc1_b + (size_t)l*FFD;
        const __half* f2w = hf2 + (size_t)l*FFD*DD; const float* f2b = fc2_b + (size_t)l*DD;

        // attention block
        k_ln<<<MM, 256>>>(x, ln1_w + (size_t)l*DD, ln1_b + (size_t)l*DD, h);
        k_hmma<<<gD, 256, HSMEM>>>(h, qw, qb, nullptr, q, MM, DD, DD, 0);
        k_hmma<<<gD, 256, HSMEM>>>(h, kw, kb, nullptr, k, MM, DD, DD, 0);
        k_hmma<<<gD, 256, HSMEM>>>(h, vw, vb, nullptr, v, MM, DD, DD, 0);
        k_scores<<<dim3(17, 17, BB*HH), dim3(16,16)>>>(q, k);
        k_softmax<<<BB*HH*SS, 256>>>();
        k_ctx<<<dim3(17, BB*HH), dim3(16,16)>>>(v, ctx);
        k_hmma<<<gD, 256, HSMEM>>>(ctx, ow, ob, x, x, MM, DD, DD, 0);   // +residual

        // MLP block
        k_ln<<<MM, 256>>>(x, ln2_w + (size_t)l*DD, ln2_b + (size_t)l*DD, h);
        k_hmma<<<gFF, 256, HSMEM>>>(h, f1w, f1b, nullptr, ff, MM, FFD, DD, 3);  // gelu->fp16
        k_hmma<<<gD, 256, HSMEM>>>(ff, f2w, f2b, x, x, MM, DD, FFD, 0);         // +residual

        // MoD top-k block: identity -> skipped
    }
    (void)in_sizes; (void)n_in; (void)out_size;
}

// round 14
// speedup vs baseline: 3.0086x; 2.0153x over previous
#include <cuda_runtime.h>
#include <cuda_fp16.h>
#include <math.h>

// Problem constants
#define BB   16
#define SS   257
#define SPAD 384
#define DD   1024
#define HH   16
#define DHH  64
#define FFD  4096
#define LLN  6
#define PPP  14
#define NPS  16
#define NP   256
#define KC   (3*14*14)   // 588 im2col K
#define MM   (BB*SS)     // 4112 rows
#define LNEPS 1e-5f

// ---------------- scratch ----------------------------------------------------
__device__ float  g_col [BB*NP*KC];
__device__ float  g_feat[BB*NP*DD];
__device__ __half g_h   [MM*DD];                  // LN output (fp16)
__device__ __half g_q16 [BB*HH*SPAD*DHH];         // head-major Q (pad rows stay 0)
__device__ __half g_k16 [BB*HH*SPAD*DHH];
__device__ __half g_v16 [BB*HH*SPAD*DHH];
__device__ __half g_ctx [MM*DD];                  // attention context (fp16)
__device__ __half g_ff  [(size_t)MM*FFD];         // MLP hidden (fp16)
// fp16 weights
__device__ __half g_hqkv[(size_t)LLN*3*DD*DD];    // [l][{q,k,v}][D][D]
__device__ float  g_bqkv[LLN*3*DD];               // packed qkv bias
__device__ __half g_ho [LLN*DD*DD];
__device__ __half g_hf1[(size_t)LLN*FFD*DD];
__device__ __half g_hf2[(size_t)LLN*FFD*DD];

// ---------------- converts / packs -------------------------------------------
__global__ void k_half(const float* __restrict__ s, __half* __restrict__ d, int n4) {
    int i = blockIdx.x * blockDim.x + threadIdx.x;
    if (i >= n4) return;
    float4 t = reinterpret_cast<const float4*>(s)[i];
    __half2* d2 = reinterpret_cast<__half2*>(d);
    d2[2*i+0] = __floats2half2_rn(t.x, t.y);
    d2[2*i+1] = __floats2half2_rn(t.z, t.w);
}

__global__ void k_packw(const float* __restrict__ s, int which) {
    const int per = DD*DD/4;
    int i = blockIdx.x * blockDim.x + threadIdx.x;
    if (i >= LLN*per) return;
    int l = i / per, r = i % per;
    float4 t = reinterpret_cast<const float4*>(s)[i];
    __half2* d2 = reinterpret_cast<__half2*>(g_hqkv + ((size_t)l*3 + which)*DD*DD);
    d2[2*r+0] = __floats2half2_rn(t.x, t.y);
    d2[2*r+1] = __floats2half2_rn(t.z, t.w);
}

__global__ void k_packb(const float* __restrict__ qb, const float* __restrict__ kb,
                        const float* __restrict__ vb) {
    int idx = blockIdx.x * blockDim.x + threadIdx.x;
    if (idx >= LLN*3*DD) return;
    int l = idx / (3*DD), r = idx % (3*DD);
    int w = r >> 10, i = r & 1023;
    const float* s = (w == 0) ? qb : (w == 1) ? kb : vb;
    g_bqkv[idx] = s[l*DD + i];
}

// ---------------- im2col -----------------------------------------------------
__global__ void k_im2col(const float* __restrict__ px) {
    int idx = blockIdx.x * blockDim.x + threadIdx.x;
    const int total = BB*NP*KC;
    if (idx >= total) return;
    int kc = idx % KC;  int bp = idx / KC;
    int p  = bp % NP;   int b  = bp / NP;
    int c  = kc / (PPP*PPP); int rem = kc % (PPP*PPP);
    int i  = rem / PPP, j = rem % PPP;
    int py = p / NPS,   pxi = p % NPS;
    int row = py*PPP + i, col = pxi*PPP + j;
    g_col[idx] = px[((size_t)(b*3 + c)*224 + row)*224 + col];
}

// ---------------- SIMT GEMM (patch-embed only, K=588, full fp32) ------------
#define TBM 64
#define TBN 64
#define TBK 16
__global__ void k_gemm(const float* __restrict__ A, const float* __restrict__ B,
                       float* __restrict__ C, int M, int N, int K) {
    __shared__ float As[TBK][TBM+4];
    __shared__ float Bs[TBK][TBN+4];
    int tid = threadIdx.x;
    int tx = tid & 15, ty = tid >> 4;
    int bm = blockIdx.y * TBM, bn = blockIdx.x * TBN;
    int lr = tid >> 2;
    int lc = (tid & 3) * 4;
    float acc[4][4] = {};

    for (int k0 = 0; k0 < K; k0 += TBK) {
        {
            int ar = bm + lr;
            if (ar < M && (k0 + lc + 3) < K) {
                float4 t = *reinterpret_cast<const float4*>(&A[(size_t)ar*K + k0 + lc]);
                As[lc+0][lr] = t.x; As[lc+1][lr] = t.y;
                As[lc+2][lr] = t.z; As[lc+3][lr] = t.w;
            } else {
                #pragma unroll
                for (int i = 0; i < 4; i++) {
                    int kk = k0 + lc + i;
                    As[lc+i][lr] = (ar < M && kk < K) ? A[(size_t)ar*K + kk] : 0.f;
                }
            }
        }
        {
            int br = bn + lr;
            if (br < N && (k0 + lc + 3) < K) {
                float4 t = *reinterpret_cast<const float4*>(&B[(size_t)br*K + k0 + lc]);
                Bs[lc+0][lr] = t.x; Bs[lc+1][lr] = t.y;
                Bs[lc+2][lr] = t.z; Bs[lc+3][lr] = t.w;
            } else {
                #pragma unroll
                for (int i = 0; i < 4; i++) {
                    int kk = k0 + lc + i;
                    Bs[lc+i][lr] = (br < N && kk < K) ? B[(size_t)br*K + kk] : 0.f;
                }
            }
        }
        __syncthreads();
        #pragma unroll
        for (int kk = 0; kk < TBK; kk++) {
            float a[4], b[4];
            #pragma unroll
            for (int i = 0; i < 4; i++) a[i] = As[kk][ty*4+i];
            #pragma unroll
            for (int j = 0; j < 4; j++) b[j] = Bs[kk][tx*4+j];
            #pragma unroll
            for (int i = 0; i < 4; i++)
                #pragma unroll
                for (int j = 0; j < 4; j++)
                    acc[i][j] += a[i] * b[j];
        }
        __syncthreads();
    }

    #pragma unroll
    for (int i = 0; i < 4; i++) {
        int r = bm + ty*4 + i;
        if (r >= M) continue;
        #pragma unroll
        for (int j = 0; j < 4; j++) {
            int c = bn + tx*4 + j;
            if (c >= N) continue;
            C[(size_t)r*N + c] = acc[i][j];
        }
    }
}

// ================ fp16 tensor-core GEMM: C = A[M,K] * B[N,K]^T ===============
#define HBM 128
#define HBN 128
#define HBK 64
#define HST 16384
#define HSMEM (4*HST)

__device__ __forceinline__ void cpa16(unsigned saddr, const void* gsrc, int bytes) {
    asm volatile("cp.async.cg.shared.global [%0], [%1], 16, %2;"
                 :: "r"(saddr), "l"(gsrc), "r"(bytes));
}
__device__ __forceinline__ void ldsm4(unsigned r[4], unsigned saddr) {
    asm volatile("ldmatrix.sync.aligned.m8n8.x4.shared.b16 {%0,%1,%2,%3}, [%4];"
                 : "=r"(r[0]), "=r"(r[1]), "=r"(r[2]), "=r"(r[3]) : "r"(saddr));
}
__device__ __forceinline__ void ldsm4t(unsigned r[4], unsigned saddr) {
    asm volatile("ldmatrix.sync.aligned.m8n8.x4.trans.shared.b16 {%0,%1,%2,%3}, [%4];"
                 : "=r"(r[0]), "=r"(r[1]), "=r"(r[2]), "=r"(r[3]) : "r"(saddr));
}
__device__ __forceinline__ void mma_f16(float c[4], const unsigned a[4],
                                        unsigned b0, unsigned b1) {
    asm volatile(
        "mma.sync.aligned.m16n8k16.row.col.f32.f16.f16.f32 "
        "{%0,%1,%2,%3}, {%4,%5,%6,%7}, {%8,%9}, {%0,%1,%2,%3};"
        : "+f"(c[0]), "+f"(c[1]), "+f"(c[2]), "+f"(c[3])
        : "r"(a[0]), "r"(a[1]), "r"(a[2]), "r"(a[3]), "r"(b0), "r"(b1));
}
__device__ __forceinline__ unsigned h2u(__half2 h) {
    unsigned u;
    __builtin_memcpy(&u, &h, 4);
    return u;
}

// act bit0: quickGELU; bit1: store fp16; bit2: QKV head-major scatter
__global__ void __launch_bounds__(256)
k_hmma(const __half* __restrict__ A, const __half* __restrict__ B,
       const float* __restrict__ bias, const float* __restrict__ add,
       void* __restrict__ Cv, int M, int N, int K, int act) {
    extern __shared__ char hsm[];
    unsigned base = (unsigned)__cvta_generic_to_shared(hsm);
    int tid = threadIdx.x;
    int lane = tid & 31, w = tid >> 5;
    int wm = w >> 2, wn = w & 3;
    int lg = lane >> 2, lt = lane & 3;
    int lr8 = lane & 7;
    int bm = blockIdx.y * HBM, bn = blockIdx.x * HBN;

    float c[4][4][4];
    #pragma unroll
    for (int i = 0; i < 4; i++)
        #pragma unroll
        for (int j = 0; j < 4; j++)
            #pragma unroll
            for (int r = 0; r < 4; r++) c[i][j][r] = 0.f;

    const int NIT = K / HBK;

    auto loadA = [&](int st, int k0) {
        #pragma unroll
        for (int t = 0; t < 4; t++) {
            int slot = tid + t*256;
            int r = slot >> 3, ch = slot & 7;
            int gr = bm + r;
            const __half* src = A + (size_t)(gr < M ? gr : 0)*K + k0 + ch*8;
            cpa16(base + st*HST + r*128u + (unsigned)((ch ^ (r & 7)) << 4),
                  src, (gr < M) ? 16 : 0);
        }
    };
    auto loadB = [&](int st, int k0) {
        #pragma unroll
        for (int t = 0; t < 4; t++) {
            int slot = tid + t*256;
            int r = slot >> 3, ch = slot & 7;
            const __half* src = B + (size_t)(bn + r)*K + k0 + ch*8;
            cpa16(base + 2*HST + st*HST + r*128u + (unsigned)((ch ^ (r & 7)) << 4),
                  src, 16);
        }
    };

    int agrp = lane >> 3;
    int arow = ((agrp & 1) << 3) + lr8;
    int akc  = agrp >> 1;
    int brow = ((lane >> 4) << 3) + lr8;
    int bkc  = (lane >> 3) & 1;

    loadA(0, 0); loadB(0, 0);
    asm volatile("cp.async.commit_group;");

    for (int it = 0; it < NIT; it++) {
        int cur = it & 1;
        if (it + 1 < NIT) {
            loadA(cur ^ 1, (it+1)*HBK);
            loadB(cur ^ 1, (it+1)*HBK);
            asm volatile("cp.async.commit_group;");
            asm volatile("cp.async.wait_group 1;");
        } else {
            asm volatile("cp.async.wait_group 0;");
        }
        __syncthreads();

        unsigned aB = base + cur*HST;
        unsigned bB = base + 2*HST + cur*HST;
        #pragma unroll
        for (int ks = 0; ks < 4; ks++) {
            unsigned a[4][4], bf[2][4];
            #pragma unroll
            for (int mt = 0; mt < 4; mt++) {
                int row = wm*64 + mt*16 + arow;
                ldsm4(a[mt], aB + (unsigned)row*128u
                              + (unsigned)(((2*ks + akc) ^ lr8) << 4));
            }
            #pragma unroll
            for (int p = 0; p < 2; p++) {
                int row = wn*32 + p*16 + brow;
                ldsm4(bf[p], bB + (unsigned)row*128u
                              + (unsigned)(((2*ks + bkc) ^ lr8) << 4));
            }
            #pragma unroll
            for (int mt = 0; mt < 4; mt++)
                #pragma unroll
                for (int nt = 0; nt < 4; nt++)
                    mma_f16(c[mt][nt], a[mt],
                            bf[nt >> 1][2*(nt & 1)], bf[nt >> 1][2*(nt & 1) + 1]);
        }
        __syncthreads();
    }

    // epilogue
    int which = bn >> 10;
    __half* qkvdst = (which == 0) ? g_q16 : (which == 1) ? g_k16 : g_v16;
    #pragma unroll
    for (int nt = 0; nt < 4; nt++) {
        int cn = bn + wn*32 + nt*8 + lt*2;
        float bb0 = 0.f, bb1 = 0.f;
        if (bias) { bb0 = bias[cn]; bb1 = bias[cn+1]; }
        int hcol = cn & 1023;
        int hh = hcol >> 6, dcol = hcol & 63;
        #pragma unroll
        for (int mt = 0; mt < 4; mt++) {
            #pragma unroll
            for (int h = 0; h < 2; h++) {
                int r = bm + wm*64 + mt*16 + lg + 8*h;
                if (r < M) {
                    float v0 = c[mt][nt][2*h+0] + bb0;
                    float v1 = c[mt][nt][2*h+1] + bb1;
                    if (act & 1) {
                        v0 = v0 / (1.f + __expf(-1.702f * v0));
                        v1 = v1 / (1.f + __expf(-1.702f * v1));
                    }
                    if (add) {
                        float2 t = *reinterpret_cast<const float2*>(&add[(size_t)r*N + cn]);
                        v0 += t.x; v1 += t.y;
                    }
                    if (act & 4) {
                        int b_ = r / SS, s_ = r % SS;
                        size_t di = ((size_t)(b_*HH + hh)*SPAD + s_)*64 + dcol;
                        *reinterpret_cast<__half2*>(&qkvdst[di]) =
                            __floats2half2_rn(v0, v1);
                    } else if (act & 2) {
                        __half* Ch = (__half*)Cv;
                        *reinterpret_cast<__half2*>(&Ch[(size_t)r*N + cn]) =
                            __floats2half2_rn(v0, v1);
                    } else {
                        float* Cf = (float*)Cv;
                        *reinterpret_cast<float2*>(&Cf[(size_t)r*N + cn]) =
                            make_float2(v0, v1);
                    }
                }
            }
        }
    }
}

// ================ fused flash attention (fp16 MMA, online softmax) ===========
// grid (5, B*H); block 128 (4 warps, 16 q-rows each); q-tile 64, kv-tile 128.
#define FAQ 64
#define FAK 128
#define FA_SMEM (8192 + 4*16384)    // Q 8KB + 2 stages x (K 16KB + V 16KB)

__global__ void __launch_bounds__(128) k_flash() {
    extern __shared__ char fsm[];
    unsigned sm = (unsigned)__cvta_generic_to_shared(fsm);
    unsigned sQ = sm, sK0 = sm + 8192, sV0 = sm + 8192 + 32768;
    int tid = threadIdx.x, lane = tid & 31, w = tid >> 5;
    int lg = lane >> 2, lt = lane & 3, lr8 = lane & 7;
    int bh = blockIdx.y;
    int q0 = blockIdx.x * FAQ;

    const __half* qg = g_q16 + ((size_t)bh*SPAD + q0)*64;
    const __half* kg = g_k16 + (size_t)bh*SPAD*64;
    const __half* vg = g_v16 + (size_t)bh*SPAD*64;

    // load Q tile (64 rows x 8 chunks), 4 chunks/thread
    #pragma unroll
    for (int t = 0; t < 4; t++) {
        int slot = tid + t*128;
        int r = slot >> 3, ch = slot & 7;
        cpa16(sQ + r*128u + (unsigned)((ch ^ (r & 7)) << 4), qg + r*64 + ch*8, 16);
    }
    auto loadKV = [&](int kt, int st) {
        #pragma unroll
        for (int t = 0; t < 8; t++) {
            int slot = tid + t*128;
            int r = slot >> 3, ch = slot & 7;
            unsigned off = r*128u + (unsigned)((ch ^ (r & 7)) << 4);
            cpa16(sK0 + st*16384u + off, kg + (size_t)(kt*FAK + r)*64 + ch*8, 16);
            cpa16(sV0 + st*16384u + off, vg + (size_t)(kt*FAK + r)*64 + ch*8, 16);
        }
    };
    loadKV(0, 0);
    asm volatile("cp.async.commit_group;");
    loadKV(1, 1);
    asm volatile("cp.async.commit_group;");

    int agrp = lane >> 3;
    int arow = ((agrp & 1) << 3) + lr8;
    int akc  = agrp >> 1;
    int brow = ((lane >> 4) << 3) + lr8;
    int bkc  = (lane >> 3) & 1;
    int vrow = lr8 + ((lane >> 3) & 1) * 8;    // trans row within k16
    int vkc  = lane >> 4;                      // trans chunk low bit

    float m_[2] = {-1e30f, -1e30f};
    float l_[2] = {0.f, 0.f};
    float o[8][4];
    #pragma unroll
    for (int i = 0; i < 8; i++)
        #pragma unroll
        for (int j = 0; j < 4; j++) o[i][j] = 0.f;

    for (int kt = 0; kt < 3; kt++) {
        int st = kt & 1;
        if (kt < 2) asm volatile("cp.async.wait_group 1;");
        else        asm volatile("cp.async.wait_group 0;");
        __syncthreads();
        unsigned sK = sK0 + st*16384u, sV = sV0 + st*16384u;

        // S = Q K^T (scaled later)
        float s[16][4];
        #pragma unroll
        for (int i = 0; i < 16; i++)
            #pragma unroll
            for (int j = 0; j < 4; j++) s[i][j] = 0.f;
        #pragma unroll
        for (int ks = 0; ks < 4; ks++) {
            unsigned a[4];
            ldsm4(a, sQ + (unsigned)(w*16 + arow)*128u
                      + (unsigned)(((2*ks + akc) ^ lr8) << 4));
            #pragma unroll
            for (int p = 0; p < 8; p++) {
                unsigned bb[4];
                ldsm4(bb, sK + (unsigned)(p*16 + brow)*128u
                          + (unsigned)(((2*ks + bkc) ^ lr8) << 4));
                mma_f16(s[2*p+0], a, bb[0], bb[1]);
                mma_f16(s[2*p+1], a, bb[2], bb[3]);
            }
        }

        // online softmax (rows lg / lg+8), P -> fp16
        unsigned ph[16][2];
        #pragma unroll
        for (int e = 0; e < 2; e++) {
            float sv[16][2];
            float mx = -1e30f;
            #pragma unroll
            for (int nt = 0; nt < 16; nt++) {
                #pragma unroll
                for (int j = 0; j < 2; j++) {
                    float v = s[nt][e*2+j] * 0.125f;
                    if (kt == 2 && (nt + lt + j) != 0) v = -1e30f;
                    sv[nt][j] = v;
                    mx = fmaxf(mx, v);
                }
            }
            mx = fmaxf(mx, __shfl_xor_sync(0xFFFFFFFF, mx, 1));
            mx = fmaxf(mx, __shfl_xor_sync(0xFFFFFFFF, mx, 2));
            float mn = fmaxf(m_[e], mx);
            float corr = __expf(m_[e] - mn);
            float rs = 0.f;
            #pragma unroll
            for (int nt = 0; nt < 16; nt++) {
                float p0 = __expf(sv[nt][0] - mn);
                float p1 = __expf(sv[nt][1] - mn);
                rs += p0 + p1;
                ph[nt][e] = h2u(__floats2half2_rn(p0, p1));
            }
            rs += __shfl_xor_sync(0xFFFFFFFF, rs, 1);
            rs += __shfl_xor_sync(0xFFFFFFFF, rs, 2);
            l_[e] = l_[e]*corr + rs;
            m_[e] = mn;
            #pragma unroll
            for (int dt = 0; dt < 8; dt++) {
                o[dt][e*2+0] *= corr;
                o[dt][e*2+1] *= corr;
            }
        }

        // O += P V
        #pragma unroll
        for (int k2 = 0; k2 < 8; k2++) {
            unsigned a2[4] = { ph[2*k2][0], ph[2*k2][1], ph[2*k2+1][0], ph[2*k2+1][1] };
            #pragma unroll
            for (int dc = 0; dc < 4; dc++) {
                unsigned bb[4];
                ldsm4t(bb, sV + (unsigned)(k2*16 + vrow)*128u
                           + (unsigned)(((dc*2 + vkc) ^ lr8) << 4));
                mma_f16(o[2*dc+0], a2, bb[0], bb[1]);
                mma_f16(o[2*dc+1], a2, bb[2], bb[3]);
            }
        }
        __syncthreads();
        if (kt == 0) {
            loadKV(2, 0);
            asm volatile("cp.async.commit_group;");
        }
    }

    // store O / l  -> g_ctx [row][D] fp16
    int b_ = bh >> 4, h_ = bh & 15;
    #pragma unroll
    for (int e = 0; e < 2; e++) {
        int srow = q0 + w*16 + lg + e*8;
        if (srow < SS) {
            float inv = 1.f / l_[e];
            __half* dst = g_ctx + ((size_t)(b_*SS + srow)*DD + h_*DHH);
            #pragma unroll
            for (int dt = 0; dt < 8; dt++) {
                *reinterpret_cast<__half2*>(&dst[dt*8 + lt*2]) =
                    __floats2half2_rn(o[dt][e*2+0]*inv, o[dt][e*2+1]*inv);
            }
        }
    }
}

// ---------------- assemble embeddings ----------------------------------------
__global__ void k_assemble(const float* __restrict__ cls,
                           const float* __restrict__ pos,
                           float* __restrict__ x) {
    int idx = blockIdx.x * blockDim.x + threadIdx.x;
    if (idx >= MM*DD) return;
    int d = idx % DD; int bs = idx / DD;
    int s = bs % SS;  int b = bs / SS;
    float v = (s == 0) ? cls[d] : g_feat[((size_t)(b*NP + s - 1))*DD + d];
    x[idx] = v + pos[(size_t)s*DD + d];
}

// ---------------- LayerNorm (fp16 output) ------------------------------------
__global__ void k_ln(const float* __restrict__ x, const float* __restrict__ w,
                     const float* __restrict__ b, __half* __restrict__ out) {
    int row = blockIdx.x;
    const float* xr = x + (size_t)row*DD;
    __shared__ float red[256];
    int t = threadIdx.x;
    float s = 0.f;
    for (int i = t; i < DD; i += 256) s += xr[i];
    red[t] = s; __syncthreads();
    for (int st = 128; st > 0; st >>= 1) { if (t < st) red[t] += red[t+st]; __syncthreads(); }
    float mean = red[0] * (1.f/DD);
    __syncthreads();
    float vs = 0.f;
    for (int i = t; i < DD; i += 256) { float d = xr[i]-mean; vs += d*d; }
    red[t] = vs; __syncthreads();
    for (int st = 128; st > 0; st >>= 1) { if (t < st) red[t] += red[t+st]; __syncthreads(); }
    float rstd = rsqrtf(red[0] * (1.f/DD) + LNEPS);
    __half* o = out + (size_t)row*DD;
    for (int i = t; i < DD; i += 256)
        o[i] = __float2half_rn((xr[i]-mean)*rstd*w[i] + b[i]);
}

// ---------------- host orchestration ------------------------------------------
extern "C" void kernel_launch(void* const* d_in, const int* in_sizes, int n_in,
                              void* d_out, int out_size) {
    const float* pixel    = (const float*)d_in[0];
    const float* patch_w  = (const float*)d_in[1];
    const float* class_e  = (const float*)d_in[2];
    const float* pos_e    = (const float*)d_in[3];
    const float* ln1_w    = (const float*)d_in[4];
    const float* ln1_b    = (const float*)d_in[5];
    const float* q_w      = (const float*)d_in[6];
    const float* q_b      = (const float*)d_in[7];
    const float* k_w      = (const float*)d_in[8];
    const float* k_b      = (const float*)d_in[9];
    const float* v_w      = (const float*)d_in[10];
    const float* v_b      = (const float*)d_in[11];
    const float* o_w      = (const float*)d_in[12];
    const float* o_b      = (const float*)d_in[13];
    const float* ln2_w    = (const float*)d_in[14];
    const float* ln2_b    = (const float*)d_in[15];
    const float* fc1_w    = (const float*)d_in[16];
    const float* fc1_b    = (const float*)d_in[17];
    const float* fc2_w    = (const float*)d_in[18];
    const float* fc2_b    = (const float*)d_in[19];
    float* x = (float*)d_out;

    float *col, *feat;
    __half *h, *ctx, *ff, *hqkv, *ho, *hf1, *hf2;
    float *bqkv;
    cudaGetSymbolAddress((void**)&col,  g_col);
    cudaGetSymbolAddress((void**)&feat, g_feat);
    cudaGetSymbolAddress((void**)&h,    g_h);
    cudaGetSymbolAddress((void**)&ctx,  g_ctx);
    cudaGetSymbolAddress((void**)&ff,   g_ff);
    cudaGetSymbolAddress((void**)&hqkv, g_hqkv);
    cudaGetSymbolAddress((void**)&bqkv, g_bqkv);
    cudaGetSymbolAddress((void**)&ho,   g_ho);
    cudaGetSymbolAddress((void**)&hf1,  g_hf1);
    cudaGetSymbolAddress((void**)&hf2,  g_hf2);

    cudaFuncSetAttribute(k_hmma,  cudaFuncAttributeMaxDynamicSharedMemorySize, HSMEM);
    cudaFuncSetAttribute(k_flash, cudaFuncAttributeMaxDynamicSharedMemorySize, FA_SMEM);

    // --- pack weights/biases (fp16) ---
    const int nQ = LLN*DD*DD/4;
    const int nF = LLN*FFD*DD/4;
    k_packw<<<(nQ+255)/256, 256>>>(q_w, 0);
    k_packw<<<(nQ+255)/256, 256>>>(k_w, 1);
    k_packw<<<(nQ+255)/256, 256>>>(v_w, 2);
    k_packb<<<(LLN*3*DD+255)/256, 256>>>(q_b, k_b, v_b);
    k_half<<<(nQ+255)/256, 256>>>(o_w,  ho,  nQ);
    k_half<<<(nF+255)/256, 256>>>(fc1_w, hf1, nF);
    k_half<<<(nF+255)/256, 256>>>(fc2_w, hf2, nF);

    // --- embeddings ---
    k_im2col<<<(BB*NP*KC + 255)/256, 256>>>(pixel);
    k_gemm<<<dim3(DD/TBN, (BB*NP + TBM-1)/TBM), 256>>>(col, patch_w, feat, BB*NP, DD, KC);
    k_assemble<<<(MM*DD + 255)/256, 256>>>(class_e, pos_e, x);

    dim3 gQKV(3*DD/HBN, (MM + HBM-1)/HBM);   // (24, 33)
    dim3 gD  (DD/HBN,   (MM + HBM-1)/HBM);   // (8, 33)
    dim3 gFF (FFD/HBN,  (MM + HBM-1)/HBM);   // (32, 33)
    dim3 gFA (5, BB*HH);                     // flash attention

    for (int l = 0; l < LLN; l++) {
        const __half* qkvw = hqkv + (size_t)l*3*DD*DD;
        const float*  qkvb = bqkv + (size_t)l*3*DD;
        const __half* ow = ho + (size_t)l*DD*DD;   const float* ob = o_b + (size_t)l*DD;
        const __half* f1w = hf1 + (size_t)l*FFD*DD; const float* f1b = fc1_b + (size_t)l*FFD;
        const __half* f2w = hf2 + (size_t)l*FFD*DD; const float* f2b = fc2_b + (size_t)l*DD;

        // attention block
        k_ln<<<MM, 256>>>(x, ln1_w + (size_t)l*DD, ln1_b + (size_t)l*DD, h);
        k_hmma<<<gQKV, 256, HSMEM>>>(h, qkvw, qkvb, nullptr, nullptr,
                                     MM, 3*DD, DD, 4);            // QKV scatter
        k_flash<<<gFA, 128, FA_SMEM>>>();
        k_hmma<<<gD, 256, HSMEM>>>(ctx, ow, ob, x, x, MM, DD, DD, 0);   // +residual

        // MLP block
        k_ln<<<MM, 256>>>(x, ln2_w + (size_t)l*DD, ln2_b + (size_t)l*DD, h);
        k_hmma<<<gFF, 256, HSMEM>>>(h, f1w, f1b, nullptr, ff, MM, FFD, DD, 3);
        k_hmma<<<gD, 256, HSMEM>>>(ff, f2w, f2b, x, x, MM, DD, FFD, 0);

        // MoD top-k block: identity -> skipped
    }
    (void)in_sizes; (void)n_in; (void)out_size;
}

// round 15
// speedup vs baseline: 3.2378x; 1.0762x over previous
#include <cuda_runtime.h>
#include <cuda_fp16.h>
#include <math.h>

// Problem constants
#define BB   16
#define SS   257
#define SPAD 384
#define DD   1024
#define HH   16
#define DHH  64
#define FFD  4096
#define LLN  6
#define PPP  14
#define NPS  16
#define NP   256
#define KC   (3*14*14)   // 588 im2col K
#define KCP  640         // padded to 64 multiple for fp16 MMA path
#define MM   (BB*SS)     // 4112 rows
#define LNEPS 1e-5f

// ---------------- scratch ----------------------------------------------------
__device__ __half g_colh[BB*NP*KCP];              // im2col, fp16, zero-padded K
__device__ __half g_hpw [DD*KCP];                 // patch weights fp16 padded
__device__ float  g_feat[BB*NP*DD];
__device__ __half g_h   [MM*DD];                  // LN output (fp16)
__device__ __half g_q16 [BB*HH*SPAD*DHH];         // head-major Q (pad rows stay 0)
__device__ __half g_k16 [BB*HH*SPAD*DHH];
__device__ __half g_v16 [BB*HH*SPAD*DHH];
__device__ __half g_ctx [MM*DD];                  // attention context (fp16)
__device__ __half g_ff  [(size_t)MM*FFD];         // MLP hidden (fp16)
// fp16 weights
__device__ __half g_hqkv[(size_t)LLN*3*DD*DD];    // [l][{q,k,v}][D][D]
__device__ float  g_bqkv[LLN*3*DD];               // packed qkv bias
__device__ __half g_ho [LLN*DD*DD];
__device__ __half g_hf1[(size_t)LLN*FFD*DD];
__device__ __half g_hf2[(size_t)LLN*FFD*DD];

// ---------------- converts / packs -------------------------------------------
__global__ void k_half(const float* __restrict__ s, __half* __restrict__ d, int n4) {
    int i = blockIdx.x * blockDim.x + threadIdx.x;
    if (i >= n4) return;
    float4 t = reinterpret_cast<const float4*>(s)[i];
    __half2* d2 = reinterpret_cast<__half2*>(d);
    d2[2*i+0] = __floats2half2_rn(t.x, t.y);
    d2[2*i+1] = __floats2half2_rn(t.z, t.w);
}

__global__ void k_packw(const float* __restrict__ s, int which) {
    const int per = DD*DD/4;
    int i = blockIdx.x * blockDim.x + threadIdx.x;
    if (i >= LLN*per) return;
    int l = i / per, r = i % per;
    float4 t = reinterpret_cast<const float4*>(s)[i];
    __half2* d2 = reinterpret_cast<__half2*>(g_hqkv + ((size_t)l*3 + which)*DD*DD);
    d2[2*r+0] = __floats2half2_rn(t.x, t.y);
    d2[2*r+1] = __floats2half2_rn(t.z, t.w);
}

__global__ void k_packb(const float* __restrict__ qb, const float* __restrict__ kb,
                        const float* __restrict__ vb) {
    int idx = blockIdx.x * blockDim.x + threadIdx.x;
    if (idx >= LLN*3*DD) return;
    int l = idx / (3*DD), r = idx % (3*DD);
    int w = r >> 10, i = r & 1023;
    const float* s = (w == 0) ? qb : (w == 1) ? kb : vb;
    g_bqkv[idx] = s[l*DD + i];
}

// pack patch_w [D][588] -> fp16 [D][640] with zero pad
__global__ void k_packpw(const float* __restrict__ s) {
    int idx = blockIdx.x * blockDim.x + threadIdx.x;
    if (idx >= DD*KCP) return;
    int row = idx / KCP, col = idx % KCP;
    g_hpw[idx] = (col < KC) ? __float2half_rn(s[row*KC + col]) : __half(0.f);
}

// ---------------- im2col (fp16, padded K) ------------------------------------
__global__ void k_im2col(const float* __restrict__ px) {
    int idx = blockIdx.x * blockDim.x + threadIdx.x;
    const int total = BB*NP*KCP;
    if (idx >= total) return;
    int kc = idx % KCP;  int bp = idx / KCP;
    if (kc >= KC) { g_colh[idx] = __half(0.f); return; }
    int p  = bp % NP;   int b  = bp / NP;
    int c  = kc / (PPP*PPP); int rem = kc % (PPP*PPP);
    int i  = rem / PPP, j = rem % PPP;
    int py = p / NPS,   pxi = p % NPS;
    int row = py*PPP + i, col = pxi*PPP + j;
    g_colh[idx] = __float2half_rn(px[((size_t)(b*3 + c)*224 + row)*224 + col]);
}

// ================ fp16 tensor-core GEMM: C = A[M,K] * B[N,K]^T ===============
#define HBM 128
#define HBN 128
#define HBK 64
#define HST 16384
#define HSMEM (4*HST)

__device__ __forceinline__ void cpa16(unsigned saddr, const void* gsrc, int bytes) {
    asm volatile("cp.async.cg.shared.global [%0], [%1], 16, %2;"
                 :: "r"(saddr), "l"(gsrc), "r"(bytes));
}
__device__ __forceinline__ void ldsm4(unsigned r[4], unsigned saddr) {
    asm volatile("ldmatrix.sync.aligned.m8n8.x4.shared.b16 {%0,%1,%2,%3}, [%4];"
                 : "=r"(r[0]), "=r"(r[1]), "=r"(r[2]), "=r"(r[3]) : "r"(saddr));
}
__device__ __forceinline__ void ldsm4t(unsigned r[4], unsigned saddr) {
    asm volatile("ldmatrix.sync.aligned.m8n8.x4.trans.shared.b16 {%0,%1,%2,%3}, [%4];"
                 : "=r"(r[0]), "=r"(r[1]), "=r"(r[2]), "=r"(r[3]) : "r"(saddr));
}
__device__ __forceinline__ void mma_f16(float c[4], const unsigned a[4],
                                        unsigned b0, unsigned b1) {
    asm volatile(
        "mma.sync.aligned.m16n8k16.row.col.f32.f16.f16.f32 "
        "{%0,%1,%2,%3}, {%4,%5,%6,%7}, {%8,%9}, {%0,%1,%2,%3};"
        : "+f"(c[0]), "+f"(c[1]), "+f"(c[2]), "+f"(c[3])
        : "r"(a[0]), "r"(a[1]), "r"(a[2]), "r"(a[3]), "r"(b0), "r"(b1));
}
__device__ __forceinline__ unsigned h2u(__half2 h) {
    unsigned u;
    __builtin_memcpy(&u, &h, 4);
    return u;
}

// act bit0: quickGELU; bit1: store fp16; bit2: QKV head-major scatter
__global__ void __launch_bounds__(256)
k_hmma(const __half* __restrict__ A, const __half* __restrict__ B,
       const float* __restrict__ bias, const float* __restrict__ add,
       void* __restrict__ Cv, int M, int N, int K, int act) {
    extern __shared__ char hsm[];
    unsigned base = (unsigned)__cvta_generic_to_shared(hsm);
    int tid = threadIdx.x;
    int lane = tid & 31, w = tid >> 5;
    int wm = w >> 2, wn = w & 3;
    int lg = lane >> 2, lt = lane & 3;
    int lr8 = lane & 7;
    int bm = blockIdx.y * HBM, bn = blockIdx.x * HBN;

    float c[4][4][4];
    #pragma unroll
    for (int i = 0; i < 4; i++)
        #pragma unroll
        for (int j = 0; j < 4; j++)
            #pragma unroll
            for (int r = 0; r < 4; r++) c[i][j][r] = 0.f;

    const int NIT = K / HBK;

    auto loadA = [&](int st, int k0) {
        #pragma unroll
        for (int t = 0; t < 4; t++) {
            int slot = tid + t*256;
            int r = slot >> 3, ch = slot & 7;
            int gr = bm + r;
            const __half* src = A + (size_t)(gr < M ? gr : 0)*K + k0 + ch*8;
            cpa16(base + st*HST + r*128u + (unsigned)((ch ^ (r & 7)) << 4),
                  src, (gr < M) ? 16 : 0);
        }
    };
    auto loadB = [&](int st, int k0) {
        #pragma unroll
        for (int t = 0; t < 4; t++) {
            int slot = tid + t*256;
            int r = slot >> 3, ch = slot & 7;
            const __half* src = B + (size_t)(bn + r)*K + k0 + ch*8;
            cpa16(base + 2*HST + st*HST + r*128u + (unsigned)((ch ^ (r & 7)) << 4),
                  src, 16);
        }
    };

    int agrp = lane >> 3;
    int arow = ((agrp & 1) << 3) + lr8;
    int akc  = agrp >> 1;
    int brow = ((lane >> 4) << 3) + lr8;
    int bkc  = (lane >> 3) & 1;

    loadA(0, 0); loadB(0, 0);
    asm volatile("cp.async.commit_group;");

    for (int it = 0; it < NIT; it++) {
        int cur = it & 1;
        if (it + 1 < NIT) {
            loadA(cur ^ 1, (it+1)*HBK);
            loadB(cur ^ 1, (it+1)*HBK);
            asm volatile("cp.async.commit_group;");
            asm volatile("cp.async.wait_group 1;");
        } else {
            asm volatile("cp.async.wait_group 0;");
        }
        __syncthreads();

        unsigned aB = base + cur*HST;
        unsigned bB = base + 2*HST + cur*HST;
        #pragma unroll
        for (int ks = 0; ks < 4; ks++) {
            unsigned a[4][4], bf[2][4];
            #pragma unroll
            for (int mt = 0; mt < 4; mt++) {
                int row = wm*64 + mt*16 + arow;
                ldsm4(a[mt], aB + (unsigned)row*128u
                              + (unsigned)(((2*ks + akc) ^ lr8) << 4));
            }
            #pragma unroll
            for (int p = 0; p < 2; p++) {
                int row = wn*32 + p*16 + brow;
                ldsm4(bf[p], bB + (unsigned)row*128u
                              + (unsigned)(((2*ks + bkc) ^ lr8) << 4));
            }
            #pragma unroll
            for (int mt = 0; mt < 4; mt++)
                #pragma unroll
                for (int nt = 0; nt < 4; nt++)
                    mma_f16(c[mt][nt], a[mt],
                            bf[nt >> 1][2*(nt & 1)], bf[nt >> 1][2*(nt & 1) + 1]);
        }
        __syncthreads();
    }

    // epilogue
    int which = bn >> 10;
    __half* qkvdst = (which == 0) ? g_q16 : (which == 1) ? g_k16 : g_v16;
    #pragma unroll
    for (int nt = 0; nt < 4; nt++) {
        int cn = bn + wn*32 + nt*8 + lt*2;
        float bb0 = 0.f, bb1 = 0.f;
        if (bias) { bb0 = bias[cn]; bb1 = bias[cn+1]; }
        int hcol = cn & 1023;
        int hh = hcol >> 6, dcol = hcol & 63;
        #pragma unroll
        for (int mt = 0; mt < 4; mt++) {
            #pragma unroll
            for (int h = 0; h < 2; h++) {
                int r = bm + wm*64 + mt*16 + lg + 8*h;
                if (r < M) {
                    float v0 = c[mt][nt][2*h+0] + bb0;
                    float v1 = c[mt][nt][2*h+1] + bb1;
                    if (act & 1) {
                        v0 = v0 / (1.f + __expf(-1.702f * v0));
                        v1 = v1 / (1.f + __expf(-1.702f * v1));
                    }
                    if (add) {
                        float2 t = *reinterpret_cast<const float2*>(&add[(size_t)r*N + cn]);
                        v0 += t.x; v1 += t.y;
                    }
                    if (act & 4) {
                        int b_ = r / SS, s_ = r % SS;
                        size_t di = ((size_t)(b_*HH + hh)*SPAD + s_)*64 + dcol;
                        *reinterpret_cast<__half2*>(&qkvdst[di]) =
                            __floats2half2_rn(v0, v1);
                    } else if (act & 2) {
                        __half* Ch = (__half*)Cv;
                        *reinterpret_cast<__half2*>(&Ch[(size_t)r*N + cn]) =
                            __floats2half2_rn(v0, v1);
                    } else {
                        float* Cf = (float*)Cv;
                        *reinterpret_cast<float2*>(&Cf[(size_t)r*N + cn]) =
                            make_float2(v0, v1);
                    }
                }
            }
        }
    }
}

// ================ fused flash attention (fp16 MMA, online softmax) ===========
// grid (5, B*H); block 128 (4 warps, 16 q-rows each); q-tile 64, kv-tile 128.
#define FAQ 64
#define FAK 128
#define FA_SMEM (8192 + 4*16384)    // Q 8KB + 2 stages x (K 16KB + V 16KB)

__global__ void __launch_bounds__(128) k_flash() {
    extern __shared__ char fsm[];
    unsigned sm = (unsigned)__cvta_generic_to_shared(fsm);
    unsigned sQ = sm, sK0 = sm + 8192, sV0 = sm + 8192 + 32768;
    int tid = threadIdx.x, lane = tid & 31, w = tid >> 5;
    int lg = lane >> 2, lt = lane & 3, lr8 = lane & 7;
    int bh = blockIdx.y;
    int q0 = blockIdx.x * FAQ;

    const __half* qg = g_q16 + ((size_t)bh*SPAD + q0)*64;
    const __half* kg = g_k16 + (size_t)bh*SPAD*64;
    const __half* vg = g_v16 + (size_t)bh*SPAD*64;

    #pragma unroll
    for (int t = 0; t < 4; t++) {
        int slot = tid + t*128;
        int r = slot >> 3, ch = slot & 7;
        cpa16(sQ + r*128u + (unsigned)((ch ^ (r & 7)) << 4), qg + r*64 + ch*8, 16);
    }
    auto loadKV = [&](int kt, int st) {
        #pragma unroll
        for (int t = 0; t < 8; t++) {
            int slot = tid + t*128;
            int r = slot >> 3, ch = slot & 7;
            unsigned off = r*128u + (unsigned)((ch ^ (r & 7)) << 4);
            cpa16(sK0 + st*16384u + off, kg + (size_t)(kt*FAK + r)*64 + ch*8, 16);
            cpa16(sV0 + st*16384u + off, vg + (size_t)(kt*FAK + r)*64 + ch*8, 16);
        }
    };
    loadKV(0, 0);
    asm volatile("cp.async.commit_group;");
    loadKV(1, 1);
    asm volatile("cp.async.commit_group;");

    int agrp = lane >> 3;
    int arow = ((agrp & 1) << 3) + lr8;
    int akc  = agrp >> 1;
    int brow = ((lane >> 4) << 3) + lr8;
    int bkc  = (lane >> 3) & 1;
    int vrow = lr8 + ((lane >> 3) & 1) * 8;
    int vkc  = lane >> 4;

    float m_[2] = {-1e30f, -1e30f};
    float l_[2] = {0.f, 0.f};
    float o[8][4];
    #pragma unroll
    for (int i = 0; i < 8; i++)
        #pragma unroll
        for (int j = 0; j < 4; j++) o[i][j] = 0.f;

    for (int kt = 0; kt < 3; kt++) {
        int st = kt & 1;
        if (kt < 2) asm volatile("cp.async.wait_group 1;");
        else        asm volatile("cp.async.wait_group 0;");
        __syncthreads();
        unsigned sK = sK0 + st*16384u, sV = sV0 + st*16384u;

        float s[16][4];
        #pragma unroll
        for (int i = 0; i < 16; i++)
            #pragma unroll
            for (int j = 0; j < 4; j++) s[i][j] = 0.f;
        #pragma unroll
        for (int ks = 0; ks < 4; ks++) {
            unsigned a[4];
            ldsm4(a, sQ + (unsigned)(w*16 + arow)*128u
                      + (unsigned)(((2*ks + akc) ^ lr8) << 4));
            #pragma unroll
            for (int p = 0; p < 8; p++) {
                unsigned bb[4];
                ldsm4(bb, sK + (unsigned)(p*16 + brow)*128u
                          + (unsigned)(((2*ks + bkc) ^ lr8) << 4));
                mma_f16(s[2*p+0], a, bb[0], bb[1]);
                mma_f16(s[2*p+1], a, bb[2], bb[3]);
            }
        }

        unsigned ph[16][2];
        #pragma unroll
        for (int e = 0; e < 2; e++) {
            float sv[16][2];
            float mx = -1e30f;
            #pragma unroll
            for (int nt = 0; nt < 16; nt++) {
                #pragma unroll
                for (int j = 0; j < 2; j++) {
                    float v = s[nt][e*2+j] * 0.125f;
                    if (kt == 2 && (nt + lt + j) != 0) v = -1e30f;
                    sv[nt][j] = v;
                    mx = fmaxf(mx, v);
                }
            }
            mx = fmaxf(mx, __shfl_xor_sync(0xFFFFFFFF, mx, 1));
            mx = fmaxf(mx, __shfl_xor_sync(0xFFFFFFFF, mx, 2));
            float mn = fmaxf(m_[e], mx);
            float corr = __expf(m_[e] - mn);
            float rs = 0.f;
            #pragma unroll
            for (int nt = 0; nt < 16; nt++) {
                float p0 = __expf(sv[nt][0] - mn);
                float p1 = __expf(sv[nt][1] - mn);
                rs += p0 + p1;
                ph[nt][e] = h2u(__floats2half2_rn(p0, p1));
            }
            rs += __shfl_xor_sync(0xFFFFFFFF, rs, 1);
            rs += __shfl_xor_sync(0xFFFFFFFF, rs, 2);
            l_[e] = l_[e]*corr + rs;
            m_[e] = mn;
            #pragma unroll
            for (int dt = 0; dt < 8; dt++) {
                o[dt][e*2+0] *= corr;
                o[dt][e*2+1] *= corr;
            }
        }

        #pragma unroll
        for (int k2 = 0; k2 < 8; k2++) {
            unsigned a2[4] = { ph[2*k2][0], ph[2*k2][1], ph[2*k2+1][0], ph[2*k2+1][1] };
            #pragma unroll
            for (int dc = 0; dc < 4; dc++) {
                unsigned bb[4];
                ldsm4t(bb, sV + (unsigned)(k2*16 + vrow)*128u
                           + (unsigned)(((dc*2 + vkc) ^ lr8) << 4));
                mma_f16(o[2*dc+0], a2, bb[0], bb[1]);
                mma_f16(o[2*dc+1], a2, bb[2], bb[3]);
            }
        }
        __syncthreads();
        if (kt == 0) {
            loadKV(2, 0);
            asm volatile("cp.async.commit_group;");
        }
    }

    int b_ = bh >> 4, h_ = bh & 15;
    #pragma unroll
    for (int e = 0; e < 2; e++) {
        int srow = q0 + w*16 + lg + e*8;
        if (srow < SS) {
            float inv = 1.f / l_[e];
            __half* dst = g_ctx + ((size_t)(b_*SS + srow)*DD + h_*DHH);
            #pragma unroll
            for (int dt = 0; dt < 8; dt++) {
                *reinterpret_cast<__half2*>(&dst[dt*8 + lt*2]) =
                    __floats2half2_rn(o[dt][e*2+0]*inv, o[dt][e*2+1]*inv);
            }
        }
    }
}

// ---------------- assemble embeddings ----------------------------------------
__global__ void k_assemble(const float* __restrict__ cls,
                           const float* __restrict__ pos,
                           float* __restrict__ x) {
    int idx = blockIdx.x * blockDim.x + threadIdx.x;
    if (idx >= MM*DD) return;
    int d = idx % DD; int bs = idx / DD;
    int s = bs % SS;  int b = bs / SS;
    float v = (s == 0) ? cls[d] : g_feat[((size_t)(b*NP + s - 1))*DD + d];
    x[idx] = v + pos[(size_t)s*DD + d];
}

// ---------------- LayerNorm: warp-per-row, register-resident ------------------
__global__ void __launch_bounds__(256) k_ln(const float* __restrict__ x,
                     const float* __restrict__ w,
                     const float* __restrict__ b, __half* __restrict__ out) {
    int row = blockIdx.x * 8 + (threadIdx.x >> 5);
    int lane = threadIdx.x & 31;
    const float* xr = x + (size_t)row*DD;
    float4 v[8];
    float s = 0.f;
    #pragma unroll
    for (int i = 0; i < 8; i++) {
        v[i] = *reinterpret_cast<const float4*>(&xr[(i*32 + lane)*4]);
        s += (v[i].x + v[i].y) + (v[i].z + v[i].w);
    }
    #pragma unroll
    for (int d = 16; d > 0; d >>= 1) s += __shfl_xor_sync(0xFFFFFFFF, s, d);
    float mean = s * (1.f/DD);
    float vs = 0.f;
    #pragma unroll
    for (int i = 0; i < 8; i++) {
        float d0 = v[i].x-mean, d1 = v[i].y-mean, d2 = v[i].z-mean, d3 = v[i].w-mean;
        vs += d0*d0 + d1*d1 + d2*d2 + d3*d3;
    }
    #pragma unroll
    for (int d = 16; d > 0; d >>= 1) vs += __shfl_xor_sync(0xFFFFFFFF, vs, d);
    float rstd = rsqrtf(vs * (1.f/DD) + LNEPS);
    __half* o = out + (size_t)row*DD;
    #pragma unroll
    for (int i = 0; i < 8; i++) {
        int c = (i*32 + lane)*4;
        float4 ww = *reinterpret_cast<const float4*>(&w[c]);
        float4 bb = *reinterpret_cast<const float4*>(&b[c]);
        __half2 h0 = __floats2half2_rn((v[i].x-mean)*rstd*ww.x + bb.x,
                                       (v[i].y-mean)*rstd*ww.y + bb.y);
        __half2 h1 = __floats2half2_rn((v[i].z-mean)*rstd*ww.z + bb.z,
                                       (v[i].w-mean)*rstd*ww.w + bb.w);
        uint2 pk; pk.x = h2u(h0); pk.y = h2u(h1);
        *reinterpret_cast<uint2*>(&o[c]) = pk;
    }
}

// ---------------- host orchestration ------------------------------------------
extern "C" void kernel_launch(void* const* d_in, const int* in_sizes, int n_in,
                              void* d_out, int out_size) {
    const float* pixel    = (const float*)d_in[0];
    const float* patch_w  = (const float*)d_in[1];
    const float* class_e  = (const float*)d_in[2];
    const float* pos_e    = (const float*)d_in[3];
    const float* ln1_w    = (const float*)d_in[4];
    const float* ln1_b    = (const float*)d_in[5];
    const float* q_w      = (const float*)d_in[6];
    const float* q_b      = (const float*)d_in[7];
    const float* k_w      = (const float*)d_in[8];
    const float* k_b      = (const float*)d_in[9];
    const float* v_w      = (const float*)d_in[10];
    const float* v_b      = (const float*)d_in[11];
    const float* o_w      = (const float*)d_in[12];
    const float* o_b      = (const float*)d_in[13];
    const float* ln2_w    = (const float*)d_in[14];
    const float* ln2_b    = (const float*)d_in[15];
    const float* fc1_w    = (const float*)d_in[16];
    const float* fc1_b    = (const float*)d_in[17];
    const float* fc2_w    = (const float*)d_in[18];
    const float* fc2_b    = (const float*)d_in[19];
    float* x = (float*)d_out;

    float *feat, *bqkv;
    __half *colh, *hpw, *h, *ctx, *ff, *hqkv, *ho, *hf1, *hf2;
    cudaGetSymbolAddress((void**)&colh, g_colh);
    cudaGetSymbolAddress((void**)&hpw,  g_hpw);
    cudaGetSymbolAddress((void**)&feat, g_feat);
    cudaGetSymbolAddress((void**)&h,    g_h);
    cudaGetSymbolAddress((void**)&ctx,  g_ctx);
    cudaGetSymbolAddress((void**)&ff,   g_ff);
    cudaGetSymbolAddress((void**)&hqkv, g_hqkv);
    cudaGetSymbolAddress((void**)&bqkv, g_bqkv);
    cudaGetSymbolAddress((void**)&ho,   g_ho);
    cudaGetSymbolAddress((void**)&hf1,  g_hf1);
    cudaGetSymbolAddress((void**)&hf2,  g_hf2);

    cudaFuncSetAttribute(k_hmma,  cudaFuncAttributeMaxDynamicSharedMemorySize, HSMEM);
    cudaFuncSetAttribute(k_flash, cudaFuncAttributeMaxDynamicSharedMemorySize, FA_SMEM);

    // --- pack weights/biases (fp16) ---
    const int nQ = LLN*DD*DD/4;
    const int nF = LLN*FFD*DD/4;
    k_packw<<<(nQ+255)/256, 256>>>(q_w, 0);
    k_packw<<<(nQ+255)/256, 256>>>(k_w, 1);
    k_packw<<<(nQ+255)/256, 256>>>(v_w, 2);
    k_packb<<<(LLN*3*DD+255)/256, 256>>>(q_b, k_b, v_b);
    k_packpw<<<(DD*KCP+255)/256, 256>>>(patch_w);
    k_half<<<(nQ+255)/256, 256>>>(o_w,  ho,  nQ);
    k_half<<<(nF+255)/256, 256>>>(fc1_w, hf1, nF);
    k_half<<<(nF+255)/256, 256>>>(fc2_w, hf2, nF);

    // --- embeddings: im2col (fp16) -> tensor-core GEMM -> assemble ---
    k_im2col<<<(BB*NP*KCP + 255)/256, 256>>>(pixel);
    k_hmma<<<dim3(DD/HBN, BB*NP/HBM), 256, HSMEM>>>(colh, hpw, nullptr, nullptr,
                                                    feat, BB*NP, DD, KCP, 0);
    k_assemble<<<(MM*DD + 255)/256, 256>>>(class_e, pos_e, x);

    dim3 gQKV(3*DD/HBN, (MM + HBM-1)/HBM);   // (24, 33)
    dim3 gD  (DD/HBN,   (MM + HBM-1)/HBM);   // (8, 33)
    dim3 gFF (FFD/HBN,  (MM + HBM-1)/HBM);   // (32, 33)
    dim3 gFA (5, BB*HH);                     // flash attention

    for (int l = 0; l < LLN; l++) {
        const __half* qkvw = hqkv + (size_t)l*3*DD*DD;
        const float*  qkvb = bqkv + (size_t)l*3*DD;
        const __half* ow = ho + (size_t)l*DD*DD;   const float* ob = o_b + (size_t)l*DD;
        const __half* f1w = hf1 + (size_t)l*FFD*DD; const float* f1b = fc1_b + (size_t)l*FFD;
        const __half* f2w = hf2 + (size_t)l*FFD*DD; const float* f2b = fc2_b + (size_t)l*DD;

        // attention block
        k_ln<<<MM/8, 256>>>(x, ln1_w + (size_t)l*DD, ln1_b + (size_t)l*DD, h);
        k_hmma<<<gQKV, 256, HSMEM>>>(h, qkvw, qkvb, nullptr, nullptr,
                                     MM, 3*DD, DD, 4);            // QKV scatter
        k_flash<<<gFA, 128, FA_SMEM>>>();
        k_hmma<<<gD, 256, HSMEM>>>(ctx, ow, ob, x, x, MM, DD, DD, 0);   // +residual

        // MLP block
        k_ln<<<MM/8, 256>>>(x, ln2_w + (size_t)l*DD, ln2_b + (size_t)l*DD, h);
        k_hmma<<<gFF, 256, HSMEM>>>(h, f1w, f1b, nullptr, ff, MM, FFD, DD, 3);
        k_hmma<<<gD, 256, HSMEM>>>(ff, f2w, f2b, x, x, MM, DD, FFD, 0);

        // MoD top-k block: identity -> skipped
    }
    (void)in_sizes; (void)n_in; (void)out_size;
}